// round 5
// baseline (speedup 1.0000x reference)
#include <cuda_runtime.h>
#include <cuda_bf16.h>
#include <cstdint>

#define BB 256
#define NN 256
#define IND 64
#define HID 128
#define NOUT 16
#define NL 3
#define NK 4
#define MM (BB*NN)
#define LN_EPS 1e-5f
#define EP 136                    // smem row pitch in u16 (272B) -> ldmatrix conflict-free
#define EPB (EP*2)                // pitch in bytes

// ------------------------------- scratch (device globals; no allocs) -------------------
__device__ float    g_y[(size_t)MM * HID];          // node-linear output fp32 (residual)
__device__ uint16_t g_yhi[(size_t)MM * HID];
__device__ uint16_t g_ylo[(size_t)MM * HID];
__device__ float    g_x[(size_t)MM * HID];          // layer output fp32
__device__ uint16_t g_xhi[(size_t)MM * HID];        // layer-input split planes (reused)
__device__ uint16_t g_xlo[(size_t)MM * HID];
__device__ uint16_t g_ewh[(size_t)NK * HID * HID];  // edge W^T [k][d][o] hi
__device__ uint16_t g_ewl[(size_t)NK * HID * HID];
__device__ uint16_t g_nwh[(size_t)NL * HID * HID];  // node W^T [l][d][o] hi (16384 stride)
__device__ uint16_t g_nwl[(size_t)NL * HID * HID];
__device__ float    g_ebsum[HID];

// ------------------------------- helpers -------------------------------
__device__ __forceinline__ void splitf(float a, uint16_t &h, uint16_t &l) {
    __nv_bfloat16 bh = __float2bfloat16(a);
    float res = a - __bfloat162float(bh);
    __nv_bfloat16 bl = __float2bfloat16(res);
    h = __bfloat16_as_ushort(bh);
    l = __bfloat16_as_ushort(bl);
}
__device__ __forceinline__ uint32_t packu(uint16_t a, uint16_t b) {
    return (uint32_t)a | ((uint32_t)b << 16);
}
__device__ __forceinline__ uint32_t cvta_s(const void* p) {
    return (uint32_t)__cvta_generic_to_shared(p);
}
__device__ __forceinline__ void ldsm_x4(uint32_t* r, uint32_t addr) {
    asm volatile("ldmatrix.sync.aligned.m8n8.x4.shared.b16 {%0,%1,%2,%3}, [%4];"
                 : "=r"(r[0]), "=r"(r[1]), "=r"(r[2]), "=r"(r[3]) : "r"(addr));
}
__device__ __forceinline__ void ldsm_x4_t(uint32_t* r, uint32_t addr) {
    asm volatile("ldmatrix.sync.aligned.m8n8.x4.trans.shared.b16 {%0,%1,%2,%3}, [%4];"
                 : "=r"(r[0]), "=r"(r[1]), "=r"(r[2]), "=r"(r[3]) : "r"(addr));
}
__device__ __forceinline__ void mma_bf16(float* c, const uint32_t* a, const uint32_t* b) {
    asm volatile("mma.sync.aligned.m16n8k16.row.col.f32.bf16.bf16.f32 "
                 "{%0,%1,%2,%3}, {%4,%5,%6,%7}, {%8,%9}, {%0,%1,%2,%3};"
                 : "+f"(c[0]), "+f"(c[1]), "+f"(c[2]), "+f"(c[3])
                 : "r"(a[0]), "r"(a[1]), "r"(a[2]), "r"(a[3]), "r"(b[0]), "r"(b[1]));
}
__device__ __forceinline__ void cp16(uint32_t dst, const void* src) {
    asm volatile("cp.async.cg.shared.global [%0], [%1], 16;" :: "r"(dst), "l"(src));
}
#define CP_COMMIT() asm volatile("cp.async.commit_group;")
#define CP_WAIT(n)  asm volatile("cp.async.wait_group %0;" :: "n"(n))

// ---------------------------------------------------------------------------------------
// prep: W [O=128][D] (optionally batched) -> transposed split planes [batch][d][o]
// ---------------------------------------------------------------------------------------
__global__ void prep_wt(const float* __restrict__ src, uint16_t* __restrict__ hi,
                        uint16_t* __restrict__ lo, int D)
{
    const int idx = blockIdx.x * 256 + threadIdx.x;     // over 128*D
    const int batch = blockIdx.y;
    const float* s = src + (size_t)batch * 128 * D;
    const int o = idx / D, d = idx % D;
    uint16_t h, l;
    splitf(s[idx], h, l);
    const size_t dst = (size_t)batch * D * 128 + (size_t)d * 128 + o;
    hi[dst] = h; lo[dst] = l;
}

__global__ void prep_feat(const float* __restrict__ f, uint16_t* __restrict__ hi,
                          uint16_t* __restrict__ lo)
{
    const int idx = blockIdx.x * 256 + threadIdx.x;     // MM*IND
    uint16_t h, l;
    splitf(f[idx], h, l);
    hi[idx] = h; lo[idx] = l;
}

__global__ void prep_ebsum(const float* __restrict__ eb, float* __restrict__ ebsum)
{
    const int h = threadIdx.x;
    ebsum[h] = eb[h] + eb[HID + h] + eb[2*HID + h] + eb[3*HID + h];
}

// ---------------------------------------------------------------------------------------
// Node linear (bf16x3 mma): Y = X @ W^T + b, X via split planes, W^T planes [d][o].
// Block: 128 rows x 128 cols, 8 warps x 16 rows. X tile + W fully smem-resident.
// ---------------------------------------------------------------------------------------
__global__ __launch_bounds__(256, 1) void lin_mma(
    const uint16_t* __restrict__ xhi, const uint16_t* __restrict__ xlo,
    const uint16_t* __restrict__ wh, const uint16_t* __restrict__ wl,
    const float* __restrict__ bias, float* __restrict__ Y,
    uint16_t* __restrict__ Yhi, uint16_t* __restrict__ Ylo, int D)
{
    extern __shared__ __align__(16) uint16_t lsm[];
    const uint32_t aX  = cvta_s(lsm);                    // 128 x EP (hi)
    const uint32_t pX  = 128 * EPB;                      // plane offset bytes
    const uint32_t aW  = aX + 2 * 128 * EPB;             // 128 x EP (hi)
    const uint32_t pW  = 128 * EPB;

    const int m0 = blockIdx.x * 128;
    const int tid = threadIdx.x, warp = tid >> 5, lane = tid & 31;
    const int rT = tid >> 4, cT = tid & 15;
    const uint32_t lds_off = (lane & 15) * EPB + ((lane >> 4) << 4);

    // stage X planes (rows 128 x D) and W planes (rows D x 128)
    const int dch = D >> 3;                              // 16B chunks per X row
    #pragma unroll
    for (int q = 0; q < 8; q++) {
        const int row = q * 16 + rT;
        if (cT < dch) {
            const size_t gi = (size_t)(m0 + row) * D + cT * 8;
            cp16(aX + row * EPB + cT * 16, xhi + gi);
            cp16(aX + pX + row * EPB + cT * 16, xlo + gi);
        }
    }
    for (int q = 0; q < (D >> 4); q++) {
        const int row = q * 16 + rT;
        const size_t gi = (size_t)row * 128 + cT * 8;
        cp16(aW + row * EPB + cT * 16, wh + gi);
        cp16(aW + pW + row * EPB + cT * 16, wl + gi);
    }
    CP_COMMIT(); CP_WAIT(0); __syncthreads();

    float macc[16][4];
    #pragma unroll
    for (int j = 0; j < 16; j++)
        #pragma unroll
        for (int t = 0; t < 4; t++) macc[j][t] = 0.f;

    for (int dc = 0; dc < (D >> 4); dc++) {
        uint32_t ah[4], al[4];
        const uint32_t axo = aX + (warp * 16 + (lane & 15)) * EPB + dc * 32 + ((lane >> 4) << 4);
        ldsm_x4(ah, axo);
        ldsm_x4(al, axo + pX);
        const uint32_t wb = aW + dc * 16 * EPB + lds_off;
        #pragma unroll
        for (int jj = 0; jj < 8; jj++) {
            uint32_t bh[4], bl[4];
            ldsm_x4_t(bh, wb + jj * 32);
            ldsm_x4_t(bl, wb + pW + jj * 32);
            #pragma unroll
            for (int tp = 0; tp < 2; tp++) {
                mma_bf16(macc[2*jj+tp], ah, &bh[2*tp]);
                mma_bf16(macc[2*jj+tp], ah, &bl[2*tp]);
                mma_bf16(macc[2*jj+tp], al, &bh[2*tp]);
            }
        }
    }

    // epilogue: +bias, write fp32 + split planes
    const int r0 = m0 + warp * 16 + (lane >> 2);
    #pragma unroll
    for (int j = 0; j < 16; j++) {
        const int col = j * 8 + (lane & 3) * 2;
        const float2 bb = *(const float2*)&bias[col];
        const float v0 = macc[j][0] + bb.x, v1 = macc[j][1] + bb.y;
        const float v2 = macc[j][2] + bb.x, v3 = macc[j][3] + bb.y;
        const size_t o0 = (size_t)r0 * HID + col;
        const size_t o1 = o0 + 8 * HID;
        *(float2*)&Y[o0] = make_float2(v0, v1);
        *(float2*)&Y[o1] = make_float2(v2, v3);
        uint16_t h0,l0,h1,l1;
        splitf(v0,h0,l0); splitf(v1,h1,l1);
        ((uint32_t*)Yhi)[o0 >> 1] = packu(h0,h1);
        ((uint32_t*)Ylo)[o0 >> 1] = packu(l0,l1);
        splitf(v2,h0,l0); splitf(v3,h1,l1);
        ((uint32_t*)Yhi)[o1 >> 1] = packu(h0,h1);
        ((uint32_t*)Ylo)[o1 >> 1] = packu(l0,l1);
    }
}

// ---------------------------------------------------------------------------------------
// Fused message passing + LN + ReLU.
// Grid (2, BB): block = 128 n-rows of one b, 8 warps x 16 rows x 128 cols.
// smem: full y tile (256 x 128, split planes) + W[k] region (prefetched during GEMM1).
// GEMM1: neigh_k (regs) = adj @ y  (adj A-frags direct from gmem; zero syncs)
// GEMM2: macc += neigh_k @ Wk^T
// Epilogue: v = y + macc + ebsum; x = relu(LN(v)); write fp32 + split planes.
// ---------------------------------------------------------------------------------------
__global__ __launch_bounds__(256, 1) void fused_mp(
    const float* __restrict__ adj, const uint16_t* __restrict__ yhi,
    const uint16_t* __restrict__ ylo, const uint16_t* __restrict__ wThi,
    const uint16_t* __restrict__ wTlo, const float* __restrict__ y,
    const float* __restrict__ ebsum, const float* __restrict__ lng,
    const float* __restrict__ lnb, float* __restrict__ xout,
    uint16_t* __restrict__ xhi, uint16_t* __restrict__ xlo)
{
    extern __shared__ __align__(16) uint16_t dsm[];
    const uint32_t aY = cvta_s(dsm);                     // 256 x EP (hi)
    const uint32_t pY = 256 * EPB;                       // lo plane offset (bytes)
    const uint32_t aW = aY + 2 * 256 * EPB;              // 128 x EP (hi)
    const uint32_t pW = 128 * EPB;

    const int b = blockIdx.y;
    const int n0 = blockIdx.x * 128;
    const int tid = threadIdx.x, warp = tid >> 5, lane = tid & 31;
    const int wrow = n0 + warp * 16;
    const int rT = tid >> 4, cT = tid & 15;
    const int ar = lane >> 2, ac = (lane & 3) * 2;
    const uint32_t lds_off = (lane & 15) * EPB + ((lane >> 4) << 4);

    // ---- stage full y tile (group 0) ----
    #pragma unroll
    for (int q = 0; q < 16; q++) {
        const int row = q * 16 + rT;
        const size_t gi = ((size_t)b * NN + row) * HID + cT * 8;
        cp16(aY + row * EPB + cT * 16, yhi + gi);
        cp16(aY + pY + row * EPB + cT * 16, ylo + gi);
    }
    CP_COMMIT();
    // ---- stage W[0] (group 1) ----
    #pragma unroll
    for (int q = 0; q < 8; q++) {
        const int row = q * 16 + rT;
        const size_t gi = (size_t)row * 128 + cT * 8;
        cp16(aW + row * EPB + cT * 16, wThi + gi);
        cp16(aW + pW + row * EPB + cT * 16, wTlo + gi);
    }
    CP_COMMIT();
    CP_WAIT(1); __syncthreads();   // y resident

    float macc[16][4];
    #pragma unroll
    for (int j = 0; j < 16; j++)
        #pragma unroll
        for (int t = 0; t < 4; t++) macc[j][t] = 0.f;

    for (int k = 0; k < NK; k++) {
        // -------- GEMM1: nacc = adj_k @ y (no syncs; y resident) --------
        float nacc[16][4];
        #pragma unroll
        for (int j = 0; j < 16; j++)
            #pragma unroll
            for (int t = 0; t < 4; t++) nacc[j][t] = 0.f;

        const float* Ap = adj + (((size_t)(b * NK + k) * NN + wrow) * NN);
        float2 adjP[2][4];
        adjP[0][0] = *(const float2*)(Ap + (size_t)ar * NN + ac);
        adjP[0][1] = *(const float2*)(Ap + (size_t)(ar+8) * NN + ac);
        adjP[0][2] = *(const float2*)(Ap + (size_t)ar * NN + ac + 8);
        adjP[0][3] = *(const float2*)(Ap + (size_t)(ar+8) * NN + ac + 8);

        #pragma unroll
        for (int mc = 0; mc < 16; mc++) {
            if (mc < 15) {
                const float* An = Ap + (mc + 1) * 16;
                adjP[(mc+1)&1][0] = *(const float2*)(An + (size_t)ar * NN + ac);
                adjP[(mc+1)&1][1] = *(const float2*)(An + (size_t)(ar+8) * NN + ac);
                adjP[(mc+1)&1][2] = *(const float2*)(An + (size_t)ar * NN + ac + 8);
                adjP[(mc+1)&1][3] = *(const float2*)(An + (size_t)(ar+8) * NN + ac + 8);
            }
            uint32_t ah[4], al[4];
            #pragma unroll
            for (int q = 0; q < 4; q++) {
                uint16_t h0,l0,h1,l1;
                splitf(adjP[mc&1][q].x, h0, l0);
                splitf(adjP[mc&1][q].y, h1, l1);
                ah[q] = packu(h0,h1); al[q] = packu(l0,l1);
            }
            const uint32_t yb = aY + mc * 16 * EPB + lds_off;
            #pragma unroll
            for (int jj = 0; jj < 8; jj++) {
                uint32_t bh[4], bl[4];
                ldsm_x4_t(bh, yb + jj * 32);
                ldsm_x4_t(bl, yb + pY + jj * 32);
                #pragma unroll
                for (int tp = 0; tp < 2; tp++) {
                    mma_bf16(nacc[2*jj+tp], ah, &bh[2*tp]);
                    mma_bf16(nacc[2*jj+tp], ah, &bl[2*tp]);
                    mma_bf16(nacc[2*jj+tp], al, &bh[2*tp]);
                }
            }
        }

        CP_WAIT(0); __syncthreads();   // W[k] resident

        // -------- GEMM2: macc += nacc @ W_k^T --------
        #pragma unroll
        for (int hc = 0; hc < 8; hc++) {
            uint32_t ah[4], al[4];
            {
                uint16_t h0,l0,h1,l1;
                splitf(nacc[2*hc][0],h0,l0);   splitf(nacc[2*hc][1],h1,l1);
                ah[0]=packu(h0,h1); al[0]=packu(l0,l1);
                splitf(nacc[2*hc][2],h0,l0);   splitf(nacc[2*hc][3],h1,l1);
                ah[1]=packu(h0,h1); al[1]=packu(l0,l1);
                splitf(nacc[2*hc+1][0],h0,l0); splitf(nacc[2*hc+1][1],h1,l1);
                ah[2]=packu(h0,h1); al[2]=packu(l0,l1);
                splitf(nacc[2*hc+1][2],h0,l0); splitf(nacc[2*hc+1][3],h1,l1);
                ah[3]=packu(h0,h1); al[3]=packu(l0,l1);
            }
            const uint32_t wb = aW + hc * 16 * EPB + lds_off;
            #pragma unroll
            for (int jj = 0; jj < 8; jj++) {
                uint32_t bh[4], bl[4];
                ldsm_x4_t(bh, wb + jj * 32);
                ldsm_x4_t(bl, wb + pW + jj * 32);
                #pragma unroll
                for (int tp = 0; tp < 2; tp++) {
                    mma_bf16(macc[2*jj+tp], ah, &bh[2*tp]);
                    mma_bf16(macc[2*jj+tp], ah, &bl[2*tp]);
                    mma_bf16(macc[2*jj+tp], al, &bh[2*tp]);
                }
            }
        }
        __syncthreads();               // all warps done reading W[k]
        if (k < NK - 1) {
            #pragma unroll
            for (int q = 0; q < 8; q++) {
                const int row = q * 16 + rT;
                const size_t gi = ((size_t)(k + 1) << 14) + (size_t)row * 128 + cT * 8;
                cp16(aW + row * EPB + cT * 16, wThi + gi);
                cp16(aW + pW + row * EPB + cT * 16, wTlo + gi);
            }
            CP_COMMIT();
        }
    }

    // -------- epilogue: residual + ebsum + LN + ReLU + split --------
    const int r0 = wrow + (lane >> 2);
    const int r1 = r0 + 8;
    // v = y + macc + ebsum, accumulate sums
    float s0 = 0.f, q0 = 0.f, s1 = 0.f, q1 = 0.f;
    #pragma unroll
    for (int j = 0; j < 16; j++) {
        const int col = j * 8 + (lane & 3) * 2;
        const float2 e = *(const float2*)&ebsum[col];
        const float2 y0 = *(const float2*)&y[((size_t)b * NN + r0) * HID + col];
        const float2 y1 = *(const float2*)&y[((size_t)b * NN + r1) * HID + col];
        macc[j][0] += y0.x + e.x;  macc[j][1] += y0.y + e.y;
        macc[j][2] += y1.x + e.x;  macc[j][3] += y1.y + e.y;
        s0 += macc[j][0] + macc[j][1];
        q0 += macc[j][0]*macc[j][0] + macc[j][1]*macc[j][1];
        s1 += macc[j][2] + macc[j][3];
        q1 += macc[j][2]*macc[j][2] + macc[j][3]*macc[j][3];
    }
    #pragma unroll
    for (int d = 1; d <= 2; d <<= 1) {
        s0 += __shfl_xor_sync(0xffffffffu, s0, d);
        q0 += __shfl_xor_sync(0xffffffffu, q0, d);
        s1 += __shfl_xor_sync(0xffffffffu, s1, d);
        q1 += __shfl_xor_sync(0xffffffffu, q1, d);
    }
    const float mu0 = s0 * (1.f/HID), mu1 = s1 * (1.f/HID);
    const float ri0 = rsqrtf(q0 * (1.f/HID) - mu0*mu0 + LN_EPS);
    const float ri1 = rsqrtf(q1 * (1.f/HID) - mu1*mu1 + LN_EPS);

    #pragma unroll
    for (int j = 0; j < 16; j++) {
        const int col = j * 8 + (lane & 3) * 2;
        const float2 gg = *(const float2*)&lng[col];
        const float2 bb = *(const float2*)&lnb[col];
        const float o0 = fmaxf((macc[j][0]-mu0)*ri0*gg.x + bb.x, 0.f);
        const float o1 = fmaxf((macc[j][1]-mu0)*ri0*gg.y + bb.y, 0.f);
        const float o2 = fmaxf((macc[j][2]-mu1)*ri1*gg.x + bb.x, 0.f);
        const float o3 = fmaxf((macc[j][3]-mu1)*ri1*gg.y + bb.y, 0.f);
        const size_t w0 = ((size_t)b * NN + r0) * HID + col;
        const size_t w1 = ((size_t)b * NN + r1) * HID + col;
        *(float2*)&xout[w0] = make_float2(o0, o1);
        *(float2*)&xout[w1] = make_float2(o2, o3);
        uint16_t h0,l0,h1,l1;
        splitf(o0,h0,l0); splitf(o1,h1,l1);
        ((uint32_t*)xhi)[w0 >> 1] = packu(h0,h1);
        ((uint32_t*)xlo)[w0 >> 1] = packu(l0,l1);
        splitf(o2,h0,l0); splitf(o3,h1,l1);
        ((uint32_t*)xhi)[w1 >> 1] = packu(h0,h1);
        ((uint32_t*)xlo)[w1 >> 1] = packu(l0,l1);
    }
}

// ---------------------------------------------------------------------------------------
__global__ void readout_kernel(const float* __restrict__ x, const float* __restrict__ oW,
                               const float* __restrict__ ob, float* __restrict__ out)
{
    const int b = blockIdx.x;
    const int h = threadIdx.x;
    float s = 0.0f;
    const float* xp = x + (size_t)b * NN * HID + h;
    #pragma unroll 8
    for (int n = 0; n < NN; n++) s += xp[(size_t)n * HID];
    __shared__ float repr[HID];
    repr[h] = s;
    __syncthreads();
    if (h < NOUT) {
        float acc = ob[h];
        #pragma unroll 8
        for (int d = 0; d < HID; d++) acc += repr[d] * oW[h * HID + d];
        out[b * NOUT + h] = acc;
    }
}

// ---------------------------------------------------------------------------------------
extern "C" void kernel_launch(void* const* d_in, const int* in_sizes, int n_in,
                              void* d_out, int out_size)
{
    const float* feat = (const float*)d_in[0];
    const float* adj  = (const float*)d_in[1];
    const float* nW[3] = {(const float*)d_in[2], (const float*)d_in[4], (const float*)d_in[6]};
    const float* nb[3] = {(const float*)d_in[3], (const float*)d_in[5], (const float*)d_in[7]};
    const float* eW  = (const float*)d_in[8];
    const float* ebp = (const float*)d_in[9];
    const float* lng = (const float*)d_in[10];
    const float* lnb = (const float*)d_in[11];
    const float* oW  = (const float*)d_in[12];
    const float* ob  = (const float*)d_in[13];

    float *y, *xb, *ebs;
    uint16_t *yhi, *ylo, *xhi, *xlo, *ewh, *ewl, *nwh, *nwl;
    cudaGetSymbolAddress((void**)&y,   g_y);
    cudaGetSymbolAddress((void**)&yhi, g_yhi);
    cudaGetSymbolAddress((void**)&ylo, g_ylo);
    cudaGetSymbolAddress((void**)&xb,  g_x);
    cudaGetSymbolAddress((void**)&xhi, g_xhi);
    cudaGetSymbolAddress((void**)&xlo, g_xlo);
    cudaGetSymbolAddress((void**)&ewh, g_ewh);
    cudaGetSymbolAddress((void**)&ewl, g_ewl);
    cudaGetSymbolAddress((void**)&nwh, g_nwh);
    cudaGetSymbolAddress((void**)&nwl, g_nwl);
    cudaGetSymbolAddress((void**)&ebs, g_ebsum);

    const int FUSED_SMEM = (2 * 256 + 2 * 128) * EPB;   // 208896 B
    const int LIN_SMEM   = 4 * 128 * EPB;               // 139264 B
    cudaFuncSetAttribute(fused_mp, cudaFuncAttributeMaxDynamicSharedMemorySize, FUSED_SMEM);
    cudaFuncSetAttribute(lin_mma,  cudaFuncAttributeMaxDynamicSharedMemorySize, LIN_SMEM);

    // weight prep: node (D=64, 128, 128) + edge (4 x D=128)
    prep_wt<<<dim3(128*IND/256, 1), 256>>>(nW[0], nwh, nwl, IND);
    prep_wt<<<dim3(128*HID/256, 1), 256>>>(nW[1], nwh + 16384, nwl + 16384, HID);
    prep_wt<<<dim3(128*HID/256, 1), 256>>>(nW[2], nwh + 32768, nwl + 32768, HID);
    prep_wt<<<dim3(128*HID/256, NK), 256>>>(eW, ewh, ewl, HID);
    prep_feat<<<MM*IND/256, 256>>>(feat, xhi, xlo);
    prep_ebsum<<<1, HID>>>(ebp, ebs);

    int D = IND;
    for (int l = 0; l < NL; l++) {
        lin_mma<<<MM/128, 256, LIN_SMEM>>>(xhi, xlo, nwh + l*16384, nwl + l*16384,
                                           nb[l], y, yhi, ylo, D);
        fused_mp<<<dim3(2, BB), 256, FUSED_SMEM>>>(adj, yhi, ylo, ewh, ewl, y, ebs,
                                                   lng + l*HID, lnb + l*HID, xb, xhi, xlo);
        D = HID;
    }
    readout_kernel<<<BB, HID>>>(xb, oW, ob, (float*)d_out);
}

// round 6
// speedup vs baseline: 1.1711x; 1.1711x over previous
#include <cuda_runtime.h>
#include <cuda_fp16.h>
#include <cstdint>

#define BB 256
#define NN 256
#define IND 64
#define HID 128
#define NOUT 16
#define NL 3
#define NK 4
#define MM (BB*NN)
#define LN_EPS 1e-5f
#define EP 136
#define EPB (EP*2)

// ------------------------------- scratch -------------------------------
__device__ uint16_t g_yhi[(size_t)MM * HID];        // y split planes (fp16 bits)
__device__ uint16_t g_ylo[(size_t)MM * HID];
__device__ float    g_x[(size_t)MM * HID];          // layer output fp32 (readout)
__device__ uint16_t g_xhi[(size_t)MM * HID];        // layer-input split planes
__device__ uint16_t g_xlo[(size_t)MM * HID];
__device__ uint16_t g_ewh[(size_t)NK * HID * HID];  // edge W^T [k][d][o] hi
__device__ uint16_t g_ewl[(size_t)NK * HID * HID];
__device__ uint16_t g_nwh[(size_t)NL * HID * HID];  // node W^T planes
__device__ uint16_t g_nwl[(size_t)NL * HID * HID];
__device__ float    g_ebsum[HID];

// ------------------------------- helpers -------------------------------
__device__ __forceinline__ void splith(float a, uint16_t &h, uint16_t &l) {
    __half hh = __float2half_rn(a);
    __half ll = __float2half_rn(a - __half2float(hh));
    h = __half_as_ushort(hh); l = __half_as_ushort(ll);
}
__device__ __forceinline__ uint32_t packu(uint16_t a, uint16_t b) {
    return (uint32_t)a | ((uint32_t)b << 16);
}
__device__ __forceinline__ uint32_t f22h2(float x, float y) {
    __half2 h = __floats2half2_rn(x, y);
    return *(uint32_t*)&h;
}
__device__ __forceinline__ float2 h2pairf(uint32_t hbits, uint32_t lbits) {
    float2 a = __half22float2(*(__half2*)&hbits);
    float2 b = __half22float2(*(__half2*)&lbits);
    return make_float2(a.x + b.x, a.y + b.y);
}
__device__ __forceinline__ uint32_t cvta_s(const void* p) {
    return (uint32_t)__cvta_generic_to_shared(p);
}
__device__ __forceinline__ void ldsm_x4(uint32_t* r, uint32_t addr) {
    asm volatile("ldmatrix.sync.aligned.m8n8.x4.shared.b16 {%0,%1,%2,%3}, [%4];"
                 : "=r"(r[0]), "=r"(r[1]), "=r"(r[2]), "=r"(r[3]) : "r"(addr));
}
__device__ __forceinline__ void ldsm_x4_t(uint32_t* r, uint32_t addr) {
    asm volatile("ldmatrix.sync.aligned.m8n8.x4.trans.shared.b16 {%0,%1,%2,%3}, [%4];"
                 : "=r"(r[0]), "=r"(r[1]), "=r"(r[2]), "=r"(r[3]) : "r"(addr));
}
__device__ __forceinline__ void mma_f16(float* c, const uint32_t* a, const uint32_t* b) {
    asm volatile("mma.sync.aligned.m16n8k16.row.col.f32.f16.f16.f32 "
                 "{%0,%1,%2,%3}, {%4,%5,%6,%7}, {%8,%9}, {%0,%1,%2,%3};"
                 : "+f"(c[0]), "+f"(c[1]), "+f"(c[2]), "+f"(c[3])
                 : "r"(a[0]), "r"(a[1]), "r"(a[2]), "r"(a[3]), "r"(b[0]), "r"(b[1]));
}
__device__ __forceinline__ void cp16(uint32_t dst, const void* src) {
    asm volatile("cp.async.cg.shared.global [%0], [%1], 16;" :: "r"(dst), "l"(src));
}
#define CP_COMMIT() asm volatile("cp.async.commit_group;")
#define CP_WAIT(n)  asm volatile("cp.async.wait_group %0;" :: "n"(n))

// ---------------------------------------------------------------------------------------
__global__ void prep_wt(const float* __restrict__ src, uint16_t* __restrict__ hi,
                        uint16_t* __restrict__ lo, int D)
{
    const int idx = blockIdx.x * 256 + threadIdx.x;
    const int batch = blockIdx.y;
    const float* s = src + (size_t)batch * 128 * D;
    const int o = idx / D, d = idx % D;
    uint16_t h, l;
    splith(s[idx], h, l);
    const size_t dst = (size_t)batch * D * 128 + (size_t)d * 128 + o;
    hi[dst] = h; lo[dst] = l;
}

__global__ void prep_feat(const float* __restrict__ f, uint16_t* __restrict__ hi,
                          uint16_t* __restrict__ lo)
{
    const int idx = blockIdx.x * 256 + threadIdx.x;
    uint16_t h, l;
    splith(f[idx], h, l);
    hi[idx] = h; lo[idx] = l;
}

__global__ void prep_ebsum(const float* __restrict__ eb, float* __restrict__ ebsum)
{
    const int h = threadIdx.x;
    ebsum[h] = eb[h] + eb[HID + h] + eb[2*HID + h] + eb[3*HID + h];
}

// ---------------------------------------------------------------------------------------
// Node linear (fp16x3 mma): Y = X @ W^T + b; X split planes, W^T split planes.
// Output: y split fp16 planes only (residual reconstructed from planes downstream).
// ---------------------------------------------------------------------------------------
__global__ __launch_bounds__(256, 1) void lin_mma(
    const uint16_t* __restrict__ xhi, const uint16_t* __restrict__ xlo,
    const uint16_t* __restrict__ wh, const uint16_t* __restrict__ wl,
    const float* __restrict__ bias,
    uint16_t* __restrict__ Yhi, uint16_t* __restrict__ Ylo, int D)
{
    extern __shared__ __align__(16) uint16_t lsm[];
    const uint32_t aX  = cvta_s(lsm);
    const uint32_t pX  = 128 * EPB;
    const uint32_t aW  = aX + 2 * 128 * EPB;
    const uint32_t pW  = 128 * EPB;

    const int m0 = blockIdx.x * 128;
    const int tid = threadIdx.x, warp = tid >> 5, lane = tid & 31;
    const int rT = tid >> 4, cT = tid & 15;
    const uint32_t lds_off = (lane & 15) * EPB + ((lane >> 4) << 4);

    const int dch = D >> 3;
    #pragma unroll
    for (int q = 0; q < 8; q++) {
        const int row = q * 16 + rT;
        if (cT < dch) {
            const size_t gi = (size_t)(m0 + row) * D + cT * 8;
            cp16(aX + row * EPB + cT * 16, xhi + gi);
            cp16(aX + pX + row * EPB + cT * 16, xlo + gi);
        }
    }
    for (int q = 0; q < (D >> 4); q++) {
        const int row = q * 16 + rT;
        const size_t gi = (size_t)row * 128 + cT * 8;
        cp16(aW + row * EPB + cT * 16, wh + gi);
        cp16(aW + pW + row * EPB + cT * 16, wl + gi);
    }
    CP_COMMIT(); CP_WAIT(0); __syncthreads();

    float macc[16][4];
    #pragma unroll
    for (int j = 0; j < 16; j++)
        #pragma unroll
        for (int t = 0; t < 4; t++) macc[j][t] = 0.f;

    for (int dc = 0; dc < (D >> 4); dc++) {
        uint32_t ah[4], al[4];
        const uint32_t axo = aX + (warp * 16 + (lane & 15)) * EPB + dc * 32 + ((lane >> 4) << 4);
        ldsm_x4(ah, axo);
        ldsm_x4(al, axo + pX);
        const uint32_t wb = aW + dc * 16 * EPB + lds_off;
        #pragma unroll
        for (int jj = 0; jj < 8; jj++) {
            uint32_t bh[4], bl[4];
            ldsm_x4_t(bh, wb + jj * 32);
            ldsm_x4_t(bl, wb + pW + jj * 32);
            #pragma unroll
            for (int tp = 0; tp < 2; tp++) {
                mma_f16(macc[2*jj+tp], ah, &bh[2*tp]);
                mma_f16(macc[2*jj+tp], ah, &bl[2*tp]);
                mma_f16(macc[2*jj+tp], al, &bh[2*tp]);
            }
        }
    }

    const int r0 = m0 + warp * 16 + (lane >> 2);
    #pragma unroll
    for (int j = 0; j < 16; j++) {
        const int col = j * 8 + (lane & 3) * 2;
        const float2 bb = *(const float2*)&bias[col];
        const float v0 = macc[j][0] + bb.x, v1 = macc[j][1] + bb.y;
        const float v2 = macc[j][2] + bb.x, v3 = macc[j][3] + bb.y;
        const size_t o0 = (size_t)r0 * HID + col;
        const size_t o1 = o0 + 8 * HID;
        uint16_t h0,l0,h1,l1;
        splith(v0,h0,l0); splith(v1,h1,l1);
        ((uint32_t*)Yhi)[o0 >> 1] = packu(h0,h1);
        ((uint32_t*)Ylo)[o0 >> 1] = packu(l0,l1);
        splith(v2,h0,l0); splith(v3,h1,l1);
        ((uint32_t*)Yhi)[o1 >> 1] = packu(h0,h1);
        ((uint32_t*)Ylo)[o1 >> 1] = packu(l0,l1);
    }
}

// ---------------------------------------------------------------------------------------
// Fused message passing + LN + ReLU (fp16, 2-product in both GEMMs).
// GEMM1: A = adj single fp16 (direct LDG frags), B = y split planes (smem-resident).
// GEMM2: A = neigh single fp16, B = W_k split planes (prefetched).
// ---------------------------------------------------------------------------------------
__global__ __launch_bounds__(256, 1) void fused_mp(
    const float* __restrict__ adj, const uint16_t* __restrict__ yhi,
    const uint16_t* __restrict__ ylo, const uint16_t* __restrict__ wThi,
    const uint16_t* __restrict__ wTlo, const float* __restrict__ ebsum,
    const float* __restrict__ lng, const float* __restrict__ lnb,
    float* __restrict__ xout, uint16_t* __restrict__ xhi, uint16_t* __restrict__ xlo)
{
    extern __shared__ __align__(16) uint16_t dsm[];
    const uint32_t aY = cvta_s(dsm);
    const uint32_t pY = 256 * EPB;
    const uint32_t aW = aY + 2 * 256 * EPB;
    const uint32_t pW = 128 * EPB;

    const int b = blockIdx.y;
    const int n0 = blockIdx.x * 128;
    const int tid = threadIdx.x, warp = tid >> 5, lane = tid & 31;
    const int wrow = n0 + warp * 16;
    const int rT = tid >> 4, cT = tid & 15;
    const int ar = lane >> 2, ac = (lane & 3) * 2;
    const uint32_t lds_off = (lane & 15) * EPB + ((lane >> 4) << 4);

    #pragma unroll
    for (int q = 0; q < 16; q++) {
        const int row = q * 16 + rT;
        const size_t gi = ((size_t)b * NN + row) * HID + cT * 8;
        cp16(aY + row * EPB + cT * 16, yhi + gi);
        cp16(aY + pY + row * EPB + cT * 16, ylo + gi);
    }
    CP_COMMIT();
    #pragma unroll
    for (int q = 0; q < 8; q++) {
        const int row = q * 16 + rT;
        const size_t gi = (size_t)row * 128 + cT * 8;
        cp16(aW + row * EPB + cT * 16, wThi + gi);
        cp16(aW + pW + row * EPB + cT * 16, wTlo + gi);
    }
    CP_COMMIT();
    CP_WAIT(1); __syncthreads();

    float macc[16][4];
    #pragma unroll
    for (int j = 0; j < 16; j++)
        #pragma unroll
        for (int t = 0; t < 4; t++) macc[j][t] = 0.f;

    for (int k = 0; k < NK; k++) {
        float nacc[16][4];
        #pragma unroll
        for (int j = 0; j < 16; j++)
            #pragma unroll
            for (int t = 0; t < 4; t++) nacc[j][t] = 0.f;

        const float* Ap = adj + (((size_t)(b * NK + k) * NN + wrow) * NN);
        float2 adjP[2][4];
        adjP[0][0] = *(const float2*)(Ap + (size_t)ar * NN + ac);
        adjP[0][1] = *(const float2*)(Ap + (size_t)(ar+8) * NN + ac);
        adjP[0][2] = *(const float2*)(Ap + (size_t)ar * NN + ac + 8);
        adjP[0][3] = *(const float2*)(Ap + (size_t)(ar+8) * NN + ac + 8);

        #pragma unroll
        for (int mc = 0; mc < 16; mc++) {
            if (mc < 15) {
                const float* An = Ap + (mc + 1) * 16;
                adjP[(mc+1)&1][0] = *(const float2*)(An + (size_t)ar * NN + ac);
                adjP[(mc+1)&1][1] = *(const float2*)(An + (size_t)(ar+8) * NN + ac);
                adjP[(mc+1)&1][2] = *(const float2*)(An + (size_t)ar * NN + ac + 8);
                adjP[(mc+1)&1][3] = *(const float2*)(An + (size_t)(ar+8) * NN + ac + 8);
            }
            uint32_t ah[4];
            #pragma unroll
            for (int q = 0; q < 4; q++)
                ah[q] = f22h2(adjP[mc&1][q].x, adjP[mc&1][q].y);
            const uint32_t yb = aY + mc * 16 * EPB + lds_off;
            #pragma unroll
            for (int jj = 0; jj < 8; jj++) {
                uint32_t bh[4], bl[4];
                ldsm_x4_t(bh, yb + jj * 32);
                ldsm_x4_t(bl, yb + pY + jj * 32);
                #pragma unroll
                for (int tp = 0; tp < 2; tp++) {
                    mma_f16(nacc[2*jj+tp], ah, &bh[2*tp]);
                    mma_f16(nacc[2*jj+tp], ah, &bl[2*tp]);
                }
            }
        }

        CP_WAIT(0); __syncthreads();

        #pragma unroll
        for (int hc = 0; hc < 8; hc++) {
            uint32_t ah[4];
            ah[0] = f22h2(nacc[2*hc][0],   nacc[2*hc][1]);
            ah[1] = f22h2(nacc[2*hc][2],   nacc[2*hc][3]);
            ah[2] = f22h2(nacc[2*hc+1][0], nacc[2*hc+1][1]);
            ah[3] = f22h2(nacc[2*hc+1][2], nacc[2*hc+1][3]);
            const uint32_t wb = aW + hc * 16 * EPB + lds_off;
            #pragma unroll
            for (int jj = 0; jj < 8; jj++) {
                uint32_t bh[4], bl[4];
                ldsm_x4_t(bh, wb + jj * 32);
                ldsm_x4_t(bl, wb + pW + jj * 32);
                #pragma unroll
                for (int tp = 0; tp < 2; tp++) {
                    mma_f16(macc[2*jj+tp], ah, &bh[2*tp]);
                    mma_f16(macc[2*jj+tp], ah, &bl[2*tp]);
                }
            }
        }
        __syncthreads();
        if (k < NK - 1) {
            #pragma unroll
            for (int q = 0; q < 8; q++) {
                const int row = q * 16 + rT;
                const size_t gi = ((size_t)(k + 1) << 14) + (size_t)row * 128 + cT * 8;
                cp16(aW + row * EPB + cT * 16, wThi + gi);
                cp16(aW + pW + row * EPB + cT * 16, wTlo + gi);
            }
            CP_COMMIT();
        }
    }

    // epilogue: residual (from y planes) + ebsum + LN + ReLU + outputs
    const int r0 = wrow + (lane >> 2);
    const int r1 = r0 + 8;
    const uint32_t* yh32 = (const uint32_t*)yhi;
    const uint32_t* yl32 = (const uint32_t*)ylo;
    float s0 = 0.f, q0 = 0.f, s1 = 0.f, q1 = 0.f;
    #pragma unroll
    for (int j = 0; j < 16; j++) {
        const int col = j * 8 + (lane & 3) * 2;
        const float2 e = *(const float2*)&ebsum[col];
        const size_t w0 = ((size_t)b * NN + r0) * HID + col;
        const size_t w1 = ((size_t)b * NN + r1) * HID + col;
        const float2 y0 = h2pairf(yh32[w0 >> 1], yl32[w0 >> 1]);
        const float2 y1 = h2pairf(yh32[w1 >> 1], yl32[w1 >> 1]);
        macc[j][0] += y0.x + e.x;  macc[j][1] += y0.y + e.y;
        macc[j][2] += y1.x + e.x;  macc[j][3] += y1.y + e.y;
        s0 += macc[j][0] + macc[j][1];
        q0 += macc[j][0]*macc[j][0] + macc[j][1]*macc[j][1];
        s1 += macc[j][2] + macc[j][3];
        q1 += macc[j][2]*macc[j][2] + macc[j][3]*macc[j][3];
    }
    #pragma unroll
    for (int d = 1; d <= 2; d <<= 1) {
        s0 += __shfl_xor_sync(0xffffffffu, s0, d);
        q0 += __shfl_xor_sync(0xffffffffu, q0, d);
        s1 += __shfl_xor_sync(0xffffffffu, s1, d);
        q1 += __shfl_xor_sync(0xffffffffu, q1, d);
    }
    const float mu0 = s0 * (1.f/HID), mu1 = s1 * (1.f/HID);
    const float ri0 = rsqrtf(q0 * (1.f/HID) - mu0*mu0 + LN_EPS);
    const float ri1 = rsqrtf(q1 * (1.f/HID) - mu1*mu1 + LN_EPS);

    #pragma unroll
    for (int j = 0; j < 16; j++) {
        const int col = j * 8 + (lane & 3) * 2;
        const float2 gg = *(const float2*)&lng[col];
        const float2 bb = *(const float2*)&lnb[col];
        const float o0 = fmaxf((macc[j][0]-mu0)*ri0*gg.x + bb.x, 0.f);
        const float o1 = fmaxf((macc[j][1]-mu0)*ri0*gg.y + bb.y, 0.f);
        const float o2 = fmaxf((macc[j][2]-mu1)*ri1*gg.x + bb.x, 0.f);
        const float o3 = fmaxf((macc[j][3]-mu1)*ri1*gg.y + bb.y, 0.f);
        const size_t w0 = ((size_t)b * NN + r0) * HID + col;
        const size_t w1 = ((size_t)b * NN + r1) * HID + col;
        *(float2*)&xout[w0] = make_float2(o0, o1);
        *(float2*)&xout[w1] = make_float2(o2, o3);
        uint16_t h0,l0,h1,l1;
        splith(o0,h0,l0); splith(o1,h1,l1);
        ((uint32_t*)xhi)[w0 >> 1] = packu(h0,h1);
        ((uint32_t*)xlo)[w0 >> 1] = packu(l0,l1);
        splith(o2,h0,l0); splith(o3,h1,l1);
        ((uint32_t*)xhi)[w1 >> 1] = packu(h0,h1);
        ((uint32_t*)xlo)[w1 >> 1] = packu(l0,l1);
    }
}

// ---------------------------------------------------------------------------------------
__global__ void readout_kernel(const float* __restrict__ x, const float* __restrict__ oW,
                               const float* __restrict__ ob, float* __restrict__ out)
{
    const int b = blockIdx.x;
    const int h = threadIdx.x;
    float s = 0.0f;
    const float* xp = x + (size_t)b * NN * HID + h;
    #pragma unroll 8
    for (int n = 0; n < NN; n++) s += xp[(size_t)n * HID];
    __shared__ float repr[HID];
    repr[h] = s;
    __syncthreads();
    if (h < NOUT) {
        float acc = ob[h];
        #pragma unroll 8
        for (int d = 0; d < HID; d++) acc += repr[d] * oW[h * HID + d];
        out[b * NOUT + h] = acc;
    }
}

// ---------------------------------------------------------------------------------------
extern "C" void kernel_launch(void* const* d_in, const int* in_sizes, int n_in,
                              void* d_out, int out_size)
{
    const float* feat = (const float*)d_in[0];
    const float* adj  = (const float*)d_in[1];
    const float* nW[3] = {(const float*)d_in[2], (const float*)d_in[4], (const float*)d_in[6]};
    const float* nb[3] = {(const float*)d_in[3], (const float*)d_in[5], (const float*)d_in[7]};
    const float* eW  = (const float*)d_in[8];
    const float* ebp = (const float*)d_in[9];
    const float* lng = (const float*)d_in[10];
    const float* lnb = (const float*)d_in[11];
    const float* oW  = (const float*)d_in[12];
    const float* ob  = (const float*)d_in[13];

    float *xb, *ebs;
    uint16_t *yhi, *ylo, *xhi, *xlo, *ewh, *ewl, *nwh, *nwl;
    cudaGetSymbolAddress((void**)&yhi, g_yhi);
    cudaGetSymbolAddress((void**)&ylo, g_ylo);
    cudaGetSymbolAddress((void**)&xb,  g_x);
    cudaGetSymbolAddress((void**)&xhi, g_xhi);
    cudaGetSymbolAddress((void**)&xlo, g_xlo);
    cudaGetSymbolAddress((void**)&ewh, g_ewh);
    cudaGetSymbolAddress((void**)&ewl, g_ewl);
    cudaGetSymbolAddress((void**)&nwh, g_nwh);
    cudaGetSymbolAddress((void**)&nwl, g_nwl);
    cudaGetSymbolAddress((void**)&ebs, g_ebsum);

    const int FUSED_SMEM = (2 * 256 + 2 * 128) * EPB;   // 208896 B
    const int LIN_SMEM   = 4 * 128 * EPB;               // 139264 B
    cudaFuncSetAttribute(fused_mp, cudaFuncAttributeMaxDynamicSharedMemorySize, FUSED_SMEM);
    cudaFuncSetAttribute(lin_mma,  cudaFuncAttributeMaxDynamicSharedMemorySize, LIN_SMEM);

    prep_wt<<<dim3(128*IND/256, 1), 256>>>(nW[0], nwh, nwl, IND);
    prep_wt<<<dim3(128*HID/256, 1), 256>>>(nW[1], nwh + 16384, nwl + 16384, HID);
    prep_wt<<<dim3(128*HID/256, 1), 256>>>(nW[2], nwh + 32768, nwl + 32768, HID);
    prep_wt<<<dim3(128*HID/256, NK), 256>>>(eW, ewh, ewl, HID);
    prep_feat<<<MM*IND/256, 256>>>(feat, xhi, xlo);
    prep_ebsum<<<1, HID>>>(ebp, ebs);

    int D = IND;
    for (int l = 0; l < NL; l++) {
        lin_mma<<<MM/128, 256, LIN_SMEM>>>(xhi, xlo, nwh + l*16384, nwl + l*16384,
                                           nb[l], yhi, ylo, D);
        fused_mp<<<dim3(2, BB), 256, FUSED_SMEM>>>(adj, yhi, ylo, ewh, ewl, ebs,
                                                   lng + l*HID, lnb + l*HID, xb, xhi, xlo);
        D = HID;
    }
    readout_kernel<<<BB, HID>>>(xb, oW, ob, (float*)d_out);
}

// round 9
// speedup vs baseline: 1.5760x; 1.3457x over previous
#include <cuda_runtime.h>
#include <cuda_fp16.h>
#include <cstdint>

#define BB 256
#define NN 256
#define IND 64
#define HID 128
#define NOUT 16
#define NL 3
#define NK 4
#define MM (BB*NN)
#define LN_EPS 1e-5f
#define EP 136
#define EPB (EP*2)

__device__ uint16_t g_yhi[(size_t)MM * HID];
__device__ uint16_t g_ylo[(size_t)MM * HID];
__device__ float    g_x[(size_t)MM * HID];
__device__ uint16_t g_xhi[(size_t)MM * HID];
__device__ uint16_t g_xlo[(size_t)MM * HID];
__device__ uint16_t g_ewh[(size_t)NK * HID * HID];
__device__ uint16_t g_nwh[(size_t)NL * HID * HID];
__device__ uint16_t g_nwl[(size_t)NL * HID * HID];
__device__ float    g_ebsum[HID];

__device__ __forceinline__ void splith(float a, uint16_t &h, uint16_t &l) {
    __half hh = __float2half_rn(a);
    __half ll = __float2half_rn(a - __half2float(hh));
    h = __half_as_ushort(hh); l = __half_as_ushort(ll);
}
__device__ __forceinline__ uint32_t packu(uint16_t a, uint16_t b) {
    return (uint32_t)a | ((uint32_t)b << 16);
}
__device__ __forceinline__ uint32_t f22h2(float x, float y) {
    __half2 h = __floats2half2_rn(x, y);
    return *(uint32_t*)&h;
}
__device__ __forceinline__ float2 h2pairf(uint32_t hbits, uint32_t lbits) {
    float2 a = __half22float2(*(__half2*)&hbits);
    float2 b = __half22float2(*(__half2*)&lbits);
    return make_float2(a.x + b.x, a.y + b.y);
}
__device__ __forceinline__ uint32_t cvta_s(const void* p) {
    return (uint32_t)__cvta_generic_to_shared(p);
}
__device__ __forceinline__ void ldsm_x4(uint32_t* r, uint32_t addr) {
    asm volatile("ldmatrix.sync.aligned.m8n8.x4.shared.b16 {%0,%1,%2,%3}, [%4];"
                 : "=r"(r[0]), "=r"(r[1]), "=r"(r[2]), "=r"(r[3]) : "r"(addr));
}
__device__ __forceinline__ void ldsm_x4_t(uint32_t* r, uint32_t addr) {
    asm volatile("ldmatrix.sync.aligned.m8n8.x4.trans.shared.b16 {%0,%1,%2,%3}, [%4];"
                 : "=r"(r[0]), "=r"(r[1]), "=r"(r[2]), "=r"(r[3]) : "r"(addr));
}
__device__ __forceinline__ void mma_f16(float* c, const uint32_t* a, const uint32_t* b) {
    asm volatile("mma.sync.aligned.m16n8k16.row.col.f32.f16.f16.f32 "
                 "{%0,%1,%2,%3}, {%4,%5,%6,%7}, {%8,%9}, {%0,%1,%2,%3};"
                 : "+f"(c[0]), "+f"(c[1]), "+f"(c[2]), "+f"(c[3])
                 : "r"(a[0]), "r"(a[1]), "r"(a[2]), "r"(a[3]), "r"(b[0]), "r"(b[1]));
}
__device__ __forceinline__ void cp16(uint32_t dst, const void* src) {
    asm volatile("cp.async.cg.shared.global [%0], [%1], 16;" :: "r"(dst), "l"(src));
}
#define CP_COMMIT() asm volatile("cp.async.commit_group;")
#define CP_WAIT(n)  asm volatile("cp.async.wait_group %0;" :: "n"(n))

// ---------------------------------------------------------------------------------------
__global__ void prep_wt_split(const float* __restrict__ src, uint16_t* __restrict__ hi,
                              uint16_t* __restrict__ lo, int D)
{
    const int idx = blockIdx.x * 256 + threadIdx.x;
    const int o = idx / D, d = idx % D;
    uint16_t h, l;
    splith(src[idx], h, l);
    const size_t dst = (size_t)d * 128 + o;
    hi[dst] = h; lo[dst] = l;
}

__global__ void prep_wt_hi(const float* __restrict__ src, uint16_t* __restrict__ hi, int D)
{
    const int idx = blockIdx.x * 256 + threadIdx.x;
    const int batch = blockIdx.y;
    const float* s = src + (size_t)batch * 128 * D;
    const int o = idx / D, d = idx % D;
    hi[(size_t)batch * D * 128 + (size_t)d * 128 + o] =
        __half_as_ushort(__float2half_rn(s[idx]));
}

__global__ void prep_feat(const float* __restrict__ f, uint16_t* __restrict__ hi,
                          uint16_t* __restrict__ lo)
{
    const int idx = blockIdx.x * 256 + threadIdx.x;
    uint16_t h, l;
    splith(f[idx], h, l);
    hi[idx] = h; lo[idx] = l;
}

__global__ void prep_ebsum(const float* __restrict__ eb, float* __restrict__ ebsum)
{
    const int h = threadIdx.x;
    ebsum[h] = eb[h] + eb[HID + h] + eb[2*HID + h] + eb[3*HID + h];
}

// ---------------------------------------------------------------------------------------
// Node linear (fp16 3-product): Y = X @ W^T + b -> split planes.
// ---------------------------------------------------------------------------------------
__global__ __launch_bounds__(256, 1) void lin_mma(
    const uint16_t* __restrict__ xhi, const uint16_t* __restrict__ xlo,
    const uint16_t* __restrict__ wh, const uint16_t* __restrict__ wl,
    const float* __restrict__ bias,
    uint16_t* __restrict__ Yhi, uint16_t* __restrict__ Ylo, int D)
{
    extern __shared__ __align__(16) uint16_t lsm[];
    const uint32_t aX  = cvta_s(lsm);
    const uint32_t pX  = 128 * EPB;
    const uint32_t aW  = aX + 2 * 128 * EPB;
    const uint32_t pW  = 128 * EPB;

    const int m0 = blockIdx.x * 128;
    const int tid = threadIdx.x, warp = tid >> 5, lane = tid & 31;
    const int rT = tid >> 4, cT = tid & 15;
    const uint32_t lds_off = (lane & 15) * EPB + ((lane >> 4) << 4);

    const int dch = D >> 3;
    #pragma unroll
    for (int q = 0; q < 8; q++) {
        const int row = q * 16 + rT;
        if (cT < dch) {
            const size_t gi = (size_t)(m0 + row) * D + cT * 8;
            cp16(aX + row * EPB + cT * 16, xhi + gi);
            cp16(aX + pX + row * EPB + cT * 16, xlo + gi);
        }
    }
    for (int q = 0; q < (D >> 4); q++) {
        const int row = q * 16 + rT;
        const size_t gi = (size_t)row * 128 + cT * 8;
        cp16(aW + row * EPB + cT * 16, wh + gi);
        cp16(aW + pW + row * EPB + cT * 16, wl + gi);
    }
    CP_COMMIT(); CP_WAIT(0); __syncthreads();

    float macc[16][4];
    #pragma unroll
    for (int j = 0; j < 16; j++)
        #pragma unroll
        for (int t = 0; t < 4; t++) macc[j][t] = 0.f;

    for (int dc = 0; dc < (D >> 4); dc++) {
        uint32_t ah[4], al[4];
        const uint32_t axo = aX + (warp * 16 + (lane & 15)) * EPB + dc * 32 + ((lane >> 4) << 4);
        ldsm_x4(ah, axo);
        ldsm_x4(al, axo + pX);
        const uint32_t wb = aW + dc * 16 * EPB + lds_off;
        #pragma unroll
        for (int jj = 0; jj < 8; jj++) {
            uint32_t bh[4], bl[4];
            ldsm_x4_t(bh, wb + jj * 32);
            ldsm_x4_t(bl, wb + pW + jj * 32);
            #pragma unroll
            for (int tp = 0; tp < 2; tp++) {
                mma_f16(macc[2*jj+tp], ah, &bh[2*tp]);
                mma_f16(macc[2*jj+tp], ah, &bl[2*tp]);
                mma_f16(macc[2*jj+tp], al, &bh[2*tp]);
            }
        }
    }

    const int r0 = m0 + warp * 16 + (lane >> 2);
    #pragma unroll
    for (int j = 0; j < 16; j++) {
        const int col = j * 8 + (lane & 3) * 2;
        const float2 bb = *(const float2*)&bias[col];
        const float v0 = macc[j][0] + bb.x, v1 = macc[j][1] + bb.y;
        const float v2 = macc[j][2] + bb.x, v3 = macc[j][3] + bb.y;
        const size_t o0 = (size_t)r0 * HID + col;
        const size_t o1 = o0 + 8 * HID;
        uint16_t h0,l0,h1,l1;
        splith(v0,h0,l0); splith(v1,h1,l1);
        ((uint32_t*)Yhi)[o0 >> 1] = packu(h0,h1);
        ((uint32_t*)Ylo)[o0 >> 1] = packu(l0,l1);
        splith(v2,h0,l0); splith(v3,h1,l1);
        ((uint32_t*)Yhi)[o1 >> 1] = packu(h0,h1);
        ((uint32_t*)Ylo)[o1 >> 1] = packu(l0,l1);
    }
}

// ---------------------------------------------------------------------------------------
// Fused message passing + LN + ReLU. Single-plane fp16 in both GEMMs (1 MMA each).
// ---------------------------------------------------------------------------------------
__global__ __launch_bounds__(256, 1) void fused_mp(
    const float* __restrict__ adj, const uint16_t* __restrict__ yhi,
    const uint16_t* __restrict__ ylo, const uint16_t* __restrict__ wThi,
    const float* __restrict__ ebsum, const float* __restrict__ lng,
    const float* __restrict__ lnb, float* __restrict__ xout,
    uint16_t* __restrict__ xhi, uint16_t* __restrict__ xlo)
{
    extern __shared__ __align__(16) uint16_t dsm[];
    const uint32_t aY = cvta_s(dsm);                 // 256 x EP (hi only)
    const uint32_t aW = aY + 256 * EPB;              // 128 x EP (hi only)

    const int b = blockIdx.y;
    const int n0 = blockIdx.x * 128;
    const int tid = threadIdx.x, warp = tid >> 5, lane = tid & 31;
    const int wrow = n0 + warp * 16;
    const int rT = tid >> 4, cT = tid & 15;
    const int ar = lane >> 2, ac = (lane & 3) * 2;
    const uint32_t lds_off = (lane & 15) * EPB + ((lane >> 4) << 4);

    #pragma unroll
    for (int q = 0; q < 16; q++) {
        const int row = q * 16 + rT;
        cp16(aY + row * EPB + cT * 16, yhi + ((size_t)b * NN + row) * HID + cT * 8);
    }
    #pragma unroll
    for (int q = 0; q < 8; q++) {
        const int row = q * 16 + rT;
        cp16(aW + row * EPB + cT * 16, wThi + (size_t)row * 128 + cT * 8);
    }
    CP_COMMIT(); CP_WAIT(0); __syncthreads();

    float macc[16][4];
    #pragma unroll
    for (int j = 0; j < 16; j++)
        #pragma unroll
        for (int t = 0; t < 4; t++) macc[j][t] = 0.f;

    for (int k = 0; k < NK; k++) {
        float nacc[16][4];
        #pragma unroll
        for (int j = 0; j < 16; j++)
            #pragma unroll
            for (int t = 0; t < 4; t++) nacc[j][t] = 0.f;

        const float* Ap = adj + (((size_t)(b * NK + k) * NN + wrow) * NN);
        float2 adjP[2][4];
        adjP[0][0] = *(const float2*)(Ap + (size_t)ar * NN + ac);
        adjP[0][1] = *(const float2*)(Ap + (size_t)(ar+8) * NN + ac);
        adjP[0][2] = *(const float2*)(Ap + (size_t)ar * NN + ac + 8);
        adjP[0][3] = *(const float2*)(Ap + (size_t)(ar+8) * NN + ac + 8);

        #pragma unroll
        for (int mc = 0; mc < 16; mc++) {
            if (mc < 15) {
                const float* An = Ap + (mc + 1) * 16;
                adjP[(mc+1)&1][0] = *(const float2*)(An + (size_t)ar * NN + ac);
                adjP[(mc+1)&1][1] = *(const float2*)(An + (size_t)(ar+8) * NN + ac);
                adjP[(mc+1)&1][2] = *(const float2*)(An + (size_t)ar * NN + ac + 8);
                adjP[(mc+1)&1][3] = *(const float2*)(An + (size_t)(ar+8) * NN + ac + 8);
            }
            uint32_t ah[4];
            #pragma unroll
            for (int q = 0; q < 4; q++)
                ah[q] = f22h2(adjP[mc&1][q].x, adjP[mc&1][q].y);
            const uint32_t yb = aY + mc * 16 * EPB + lds_off;
            #pragma unroll
            for (int jj = 0; jj < 8; jj++) {
                uint32_t bh[4];
                ldsm_x4_t(bh, yb + jj * 32);
                mma_f16(nacc[2*jj],   ah, &bh[0]);
                mma_f16(nacc[2*jj+1], ah, &bh[2]);
            }
        }

        CP_WAIT(0); __syncthreads();   // W[k] resident (prefetch from prior iter)

        #pragma unroll
        for (int hc = 0; hc < 8; hc++) {
            uint32_t ah[4];
            ah[0] = f22h2(nacc[2*hc][0],   nacc[2*hc][1]);
            ah[1] = f22h2(nacc[2*hc][2],   nacc[2*hc][3]);
            ah[2] = f22h2(nacc[2*hc+1][0], nacc[2*hc+1][1]);
            ah[3] = f22h2(nacc[2*hc+1][2], nacc[2*hc+1][3]);
            const uint32_t wb = aW + hc * 16 * EPB + lds_off;
            #pragma unroll
            for (int jj = 0; jj < 8; jj++) {
                uint32_t bh[4];
                ldsm_x4_t(bh, wb + jj * 32);
                mma_f16(macc[2*jj],   ah, &bh[0]);
                mma_f16(macc[2*jj+1], ah, &bh[2]);
            }
        }
        __syncthreads();
        if (k < NK - 1) {
            #pragma unroll
            for (int q = 0; q < 8; q++) {
                const int row = q * 16 + rT;
                cp16(aW + row * EPB + cT * 16,
                     wThi + ((size_t)(k + 1) << 14) + (size_t)row * 128 + cT * 8);
            }
            CP_COMMIT();
        }
    }

    // epilogue
    const int r0 = wrow + (lane >> 2);
    const int r1 = r0 + 8;
    const uint32_t* yh32 = (const uint32_t*)yhi;
    const uint32_t* yl32 = (const uint32_t*)ylo;
    float s0 = 0.f, q0 = 0.f, s1 = 0.f, q1 = 0.f;
    #pragma unroll
    for (int j = 0; j < 16; j++) {
        const int col = j * 8 + (lane & 3) * 2;
        const float2 e = *(const float2*)&ebsum[col];
        const size_t w0 = ((size_t)b * NN + r0) * HID + col;
        const size_t w1 = ((size_t)b * NN + r1) * HID + col;
        const float2 y0 = h2pairf(yh32[w0 >> 1], yl32[w0 >> 1]);
        const float2 y1 = h2pairf(yh32[w1 >> 1], yl32[w1 >> 1]);
        macc[j][0] += y0.x + e.x;  macc[j][1] += y0.y + e.y;
        macc[j][2] += y1.x + e.x;  macc[j][3] += y1.y + e.y;
        s0 += macc[j][0] + macc[j][1];
        q0 += macc[j][0]*macc[j][0] + macc[j][1]*macc[j][1];
        s1 += macc[j][2] + macc[j][3];
        q1 += macc[j][2]*macc[j][2] + macc[j][3]*macc[j][3];
    }
    #pragma unroll
    for (int d = 1; d <= 2; d <<= 1) {
        s0 += __shfl_xor_sync(0xffffffffu, s0, d);
        q0 += __shfl_xor_sync(0xffffffffu, q0, d);
        s1 += __shfl_xor_sync(0xffffffffu, s1, d);
        q1 += __shfl_xor_sync(0xffffffffu, q1, d);
    }
    const float mu0 = s0 * (1.f/HID), mu1 = s1 * (1.f/HID);
    const float ri0 = rsqrtf(q0 * (1.f/HID) - mu0*mu0 + LN_EPS);
    const float ri1 = rsqrtf(q1 * (1.f/HID) - mu1*mu1 + LN_EPS);

    #pragma unroll
    for (int j = 0; j < 16; j++) {
        const int col = j * 8 + (lane & 3) * 2;
        const float2 gg = *(const float2*)&lng[col];
        const float2 bb = *(const float2*)&lnb[col];
        const float o0 = fmaxf((macc[j][0]-mu0)*ri0*gg.x + bb.x, 0.f);
        const float o1 = fmaxf((macc[j][1]-mu0)*ri0*gg.y + bb.y, 0.f);
        const float o2 = fmaxf((macc[j][2]-mu1)*ri1*gg.x + bb.x, 0.f);
        const float o3 = fmaxf((macc[j][3]-mu1)*ri1*gg.y + bb.y, 0.f);
        const size_t w0 = ((size_t)b * NN + r0) * HID + col;
        const size_t w1 = ((size_t)b * NN + r1) * HID + col;
        *(float2*)&xout[w0] = make_float2(o0, o1);
        *(float2*)&xout[w1] = make_float2(o2, o3);
        uint16_t h0,l0,h1,l1;
        splith(o0,h0,l0); splith(o1,h1,l1);
        ((uint32_t*)xhi)[w0 >> 1] = packu(h0,h1);
        ((uint32_t*)xlo)[w0 >> 1] = packu(l0,l1);
        splith(o2,h0,l0); splith(o3,h1,l1);
        ((uint32_t*)xhi)[w1 >> 1] = packu(h0,h1);
        ((uint32_t*)xlo)[w1 >> 1] = packu(l0,l1);
    }
}

// ---------------------------------------------------------------------------------------
__global__ void readout_kernel(const float* __restrict__ x, const float* __restrict__ oW,
                               const float* __restrict__ ob, float* __restrict__ out)
{
    const int b = blockIdx.x;
    const int h = threadIdx.x;
    float s = 0.0f;
    const float* xp = x + (size_t)b * NN * HID + h;
    #pragma unroll 8
    for (int n = 0; n < NN; n++) s += xp[(size_t)n * HID];
    __shared__ float repr[HID];
    repr[h] = s;
    __syncthreads();
    if (h < NOUT) {
        float acc = ob[h];
        #pragma unroll 8
        for (int d = 0; d < HID; d++) acc += repr[d] * oW[h * HID + d];
        out[b * NOUT + h] = acc;
    }
}

// ---------------------------------------------------------------------------------------
extern "C" void kernel_launch(void* const* d_in, const int* in_sizes, int n_in,
                              void* d_out, int out_size)
{
    const float* feat = (const float*)d_in[0];
    const float* adj  = (const float*)d_in[1];
    const float* nW[3] = {(const float*)d_in[2], (const float*)d_in[4], (const float*)d_in[6]};
    const float* nb[3] = {(const float*)d_in[3], (const float*)d_in[5], (const float*)d_in[7]};
    const float* eW  = (const float*)d_in[8];
    const float* ebp = (const float*)d_in[9];
    const float* lng = (const float*)d_in[10];
    const float* lnb = (const float*)d_in[11];
    const float* oW  = (const float*)d_in[12];
    const float* ob  = (const float*)d_in[13];

    float *xb, *ebs;
    uint16_t *yhi, *ylo, *xhi, *xlo, *ewh, *nwh, *nwl;
    cudaGetSymbolAddress((void**)&yhi, g_yhi);
    cudaGetSymbolAddress((void**)&ylo, g_ylo);
    cudaGetSymbolAddress((void**)&xb,  g_x);
    cudaGetSymbolAddress((void**)&xhi, g_xhi);
    cudaGetSymbolAddress((void**)&xlo, g_xlo);
    cudaGetSymbolAddress((void**)&ewh, g_ewh);
    cudaGetSymbolAddress((void**)&nwh, g_nwh);
    cudaGetSymbolAddress((void**)&nwl, g_nwl);
    cudaGetSymbolAddress((void**)&ebs, g_ebsum);

    const int FUSED_SMEM = (256 + 128) * EPB;   // 104448 B
    const int LIN_SMEM   = 4 * 128 * EPB;       // 139264 B
    cudaFuncSetAttribute(fused_mp, cudaFuncAttributeMaxDynamicSharedMemorySize, FUSED_SMEM);
    cudaFuncSetAttribute(lin_mma,  cudaFuncAttributeMaxDynamicSharedMemorySize, LIN_SMEM);

    prep_wt_split<<<128*IND/256, 256>>>(nW[0], nwh, nwl, IND);
    prep_wt_split<<<128*HID/256, 256>>>(nW[1], nwh + 16384, nwl + 16384, HID);
    prep_wt_split<<<128*HID/256, 256>>>(nW[2], nwh + 32768, nwl + 32768, HID);
    prep_wt_hi<<<dim3(128*HID/256, NK), 256>>>(eW, ewh, HID);
    prep_feat<<<MM*IND/256, 256>>>(feat, xhi, xlo);
    prep_ebsum<<<1, HID>>>(ebp, ebs);

    int D = IND;
    for (int l = 0; l < NL; l++) {
        lin_mma<<<MM/128, 256, LIN_SMEM>>>(xhi, xlo, nwh + l*16384, nwl + l*16384,
                                           nb[l], yhi, ylo, D);
        fused_mp<<<dim3(2, BB), 256, FUSED_SMEM>>>(adj, yhi, ylo, ewh, ebs,
                                                   lng + l*HID, lnb + l*HID, xb, xhi, xlo);
        D = HID;
    }
    readout_kernel<<<BB, HID>>>(xb, oW, ob, (float*)d_out);
}

// round 10
// speedup vs baseline: 1.6021x; 1.0166x over previous
#include <cuda_runtime.h>
#include <cuda_fp16.h>
#include <cstdint>

#define BB 256
#define NN 256
#define IND 64
#define HID 128
#define NOUT 16
#define NL 3
#define NK 4
#define MM (BB*NN)
#define LN_EPS 1e-5f
#define EP 136
#define EPB (EP*2)

__device__ uint16_t g_yhi[(size_t)MM * HID];
__device__ uint16_t g_ylo[(size_t)MM * HID];
__device__ float    g_x[(size_t)MM * HID];
__device__ uint16_t g_xhi[(size_t)MM * HID];
__device__ uint16_t g_xlo[(size_t)MM * HID];
__device__ uint16_t g_ewh[(size_t)NK * HID * HID];
__device__ uint16_t g_nwh[(size_t)NL * HID * HID];
__device__ uint16_t g_nwl[(size_t)NL * HID * HID];
__device__ float    g_ebsum[HID];

__device__ __forceinline__ void splith(float a, uint16_t &h, uint16_t &l) {
    __half hh = __float2half_rn(a);
    __half ll = __float2half_rn(a - __half2float(hh));
    h = __half_as_ushort(hh); l = __half_as_ushort(ll);
}
__device__ __forceinline__ uint32_t packu(uint16_t a, uint16_t b) {
    return (uint32_t)a | ((uint32_t)b << 16);
}
__device__ __forceinline__ uint32_t f22h2(float x, float y) {
    __half2 h = __floats2half2_rn(x, y);
    return *(uint32_t*)&h;
}
__device__ __forceinline__ float2 h2pairf(uint32_t hbits, uint32_t lbits) {
    float2 a = __half22float2(*(__half2*)&hbits);
    float2 b = __half22float2(*(__half2*)&lbits);
    return make_float2(a.x + b.x, a.y + b.y);
}
__device__ __forceinline__ uint32_t cvta_s(const void* p) {
    return (uint32_t)__cvta_generic_to_shared(p);
}
__device__ __forceinline__ void ldsm_x4(uint32_t* r, uint32_t addr) {
    asm volatile("ldmatrix.sync.aligned.m8n8.x4.shared.b16 {%0,%1,%2,%3}, [%4];"
                 : "=r"(r[0]), "=r"(r[1]), "=r"(r[2]), "=r"(r[3]) : "r"(addr));
}
__device__ __forceinline__ void ldsm_x4_t(uint32_t* r, uint32_t addr) {
    asm volatile("ldmatrix.sync.aligned.m8n8.x4.trans.shared.b16 {%0,%1,%2,%3}, [%4];"
                 : "=r"(r[0]), "=r"(r[1]), "=r"(r[2]), "=r"(r[3]) : "r"(addr));
}
__device__ __forceinline__ void mma_f16(float* c, const uint32_t* a, const uint32_t* b) {
    asm volatile("mma.sync.aligned.m16n8k16.row.col.f32.f16.f16.f32 "
                 "{%0,%1,%2,%3}, {%4,%5,%6,%7}, {%8,%9}, {%0,%1,%2,%3};"
                 : "+f"(c[0]), "+f"(c[1]), "+f"(c[2]), "+f"(c[3])
                 : "r"(a[0]), "r"(a[1]), "r"(a[2]), "r"(a[3]), "r"(b[0]), "r"(b[1]));
}
__device__ __forceinline__ void cp16(uint32_t dst, const void* src) {
    asm volatile("cp.async.cg.shared.global [%0], [%1], 16;" :: "r"(dst), "l"(src));
}
#define CP_COMMIT() asm volatile("cp.async.commit_group;")
#define CP_WAIT(n)  asm volatile("cp.async.wait_group %0;" :: "n"(n))

// ---------------------------------------------------------------------------------------
__global__ void prep_wt_split(const float* __restrict__ src, uint16_t* __restrict__ hi,
                              uint16_t* __restrict__ lo, int D)
{
    const int idx = blockIdx.x * 256 + threadIdx.x;
    const int o = idx / D, d = idx % D;
    uint16_t h, l;
    splith(src[idx], h, l);
    const size_t dst = (size_t)d * 128 + o;
    hi[dst] = h; lo[dst] = l;
}

__global__ void prep_wt_hi(const float* __restrict__ src, uint16_t* __restrict__ hi, int D)
{
    const int idx = blockIdx.x * 256 + threadIdx.x;
    const int batch = blockIdx.y;
    const float* s = src + (size_t)batch * 128 * D;
    const int o = idx / D, d = idx % D;
    hi[(size_t)batch * D * 128 + (size_t)d * 128 + o] =
        __half_as_ushort(__float2half_rn(s[idx]));
}

__global__ void prep_feat(const float* __restrict__ f, uint16_t* __restrict__ hi,
                          uint16_t* __restrict__ lo)
{
    const int idx = blockIdx.x * 256 + threadIdx.x;
    uint16_t h, l;
    splith(f[idx], h, l);
    hi[idx] = h; lo[idx] = l;
}

__global__ void prep_ebsum(const float* __restrict__ eb, float* __restrict__ ebsum)
{
    const int h = threadIdx.x;
    ebsum[h] = eb[h] + eb[HID + h] + eb[2*HID + h] + eb[3*HID + h];
}

// ---------------------------------------------------------------------------------------
// Node linear (fp16 3-product): Y = X @ W^T + b -> split planes. (unchanged, validated)
// ---------------------------------------------------------------------------------------
__global__ __launch_bounds__(256, 1) void lin_mma(
    const uint16_t* __restrict__ xhi, const uint16_t* __restrict__ xlo,
    const uint16_t* __restrict__ wh, const uint16_t* __restrict__ wl,
    const float* __restrict__ bias,
    uint16_t* __restrict__ Yhi, uint16_t* __restrict__ Ylo, int D)
{
    extern __shared__ __align__(16) uint16_t lsm[];
    const uint32_t aX  = cvta_s(lsm);
    const uint32_t pX  = 128 * EPB;
    const uint32_t aW  = aX + 2 * 128 * EPB;
    const uint32_t pW  = 128 * EPB;

    const int m0 = blockIdx.x * 128;
    const int tid = threadIdx.x, warp = tid >> 5, lane = tid & 31;
    const int rT = tid >> 4, cT = tid & 15;
    const uint32_t lds_off = (lane & 15) * EPB + ((lane >> 4) << 4);

    const int dch = D >> 3;
    #pragma unroll
    for (int q = 0; q < 8; q++) {
        const int row = q * 16 + rT;
        if (cT < dch) {
            const size_t gi = (size_t)(m0 + row) * D + cT * 8;
            cp16(aX + row * EPB + cT * 16, xhi + gi);
            cp16(aX + pX + row * EPB + cT * 16, xlo + gi);
        }
    }
    for (int q = 0; q < (D >> 4); q++) {
        const int row = q * 16 + rT;
        const size_t gi = (size_t)row * 128 + cT * 8;
        cp16(aW + row * EPB + cT * 16, wh + gi);
        cp16(aW + pW + row * EPB + cT * 16, wl + gi);
    }
    CP_COMMIT(); CP_WAIT(0); __syncthreads();

    float macc[16][4];
    #pragma unroll
    for (int j = 0; j < 16; j++)
        #pragma unroll
        for (int t = 0; t < 4; t++) macc[j][t] = 0.f;

    for (int dc = 0; dc < (D >> 4); dc++) {
        uint32_t ah[4], al[4];
        const uint32_t axo = aX + (warp * 16 + (lane & 15)) * EPB + dc * 32 + ((lane >> 4) << 4);
        ldsm_x4(ah, axo);
        ldsm_x4(al, axo + pX);
        const uint32_t wb = aW + dc * 16 * EPB + lds_off;
        #pragma unroll
        for (int jj = 0; jj < 8; jj++) {
            uint32_t bh[4], bl[4];
            ldsm_x4_t(bh, wb + jj * 32);
            ldsm_x4_t(bl, wb + pW + jj * 32);
            #pragma unroll
            for (int tp = 0; tp < 2; tp++) {
                mma_f16(macc[2*jj+tp], ah, &bh[2*tp]);
                mma_f16(macc[2*jj+tp], ah, &bl[2*tp]);
                mma_f16(macc[2*jj+tp], al, &bh[2*tp]);
            }
        }
    }

    const int r0 = m0 + warp * 16 + (lane >> 2);
    #pragma unroll
    for (int j = 0; j < 16; j++) {
        const int col = j * 8 + (lane & 3) * 2;
        const float2 bb = *(const float2*)&bias[col];
        const float v0 = macc[j][0] + bb.x, v1 = macc[j][1] + bb.y;
        const float v2 = macc[j][2] + bb.x, v3 = macc[j][3] + bb.y;
        const size_t o0 = (size_t)r0 * HID + col;
        const size_t o1 = o0 + 8 * HID;
        uint16_t h0,l0,h1,l1;
        splith(v0,h0,l0); splith(v1,h1,l1);
        ((uint32_t*)Yhi)[o0 >> 1] = packu(h0,h1);
        ((uint32_t*)Ylo)[o0 >> 1] = packu(l0,l1);
        splith(v2,h0,l0); splith(v3,h1,l1);
        ((uint32_t*)Yhi)[o1 >> 1] = packu(h0,h1);
        ((uint32_t*)Ylo)[o1 >> 1] = packu(l0,l1);
    }
}

// ---------------------------------------------------------------------------------------
// Fused message passing + LN + ReLU. Single-plane fp16, deep adj prefetch.
// last=0: write split planes only (feeds next layer). last=1: write fp32 only (readout).
// ---------------------------------------------------------------------------------------
__global__ __launch_bounds__(256, 1) void fused_mp(
    const float* __restrict__ adj, const uint16_t* __restrict__ yhi,
    const uint16_t* __restrict__ ylo, const uint16_t* __restrict__ wThi,
    const float* __restrict__ ebsum, const float* __restrict__ lng,
    const float* __restrict__ lnb, float* __restrict__ xout,
    uint16_t* __restrict__ xhi, uint16_t* __restrict__ xlo, int last)
{
    extern __shared__ __align__(16) uint16_t dsm[];
    const uint32_t aY = cvta_s(dsm);                 // 256 x EP (hi only)
    const uint32_t aW = aY + 256 * EPB;              // 128 x EP (hi only)

    const int b = blockIdx.y;
    const int n0 = blockIdx.x * 128;
    const int tid = threadIdx.x, warp = tid >> 5, lane = tid & 31;
    const int wrow = n0 + warp * 16;
    const int rT = tid >> 4, cT = tid & 15;
    const int ar = lane >> 2, ac = (lane & 3) * 2;
    const uint32_t lds_off = (lane & 15) * EPB + ((lane >> 4) << 4);

    float2 adjP[2][4];
#define ADJ_LD(BUF_, KK_, MCC_) do {                                                     \
    const float* An_ = adj + (((size_t)(b * NK + (KK_)) * NN + wrow) * NN) + (MCC_) * 16;\
    adjP[BUF_][0] = *(const float2*)(An_ + (size_t)ar * NN + ac);                        \
    adjP[BUF_][1] = *(const float2*)(An_ + (size_t)(ar+8) * NN + ac);                    \
    adjP[BUF_][2] = *(const float2*)(An_ + (size_t)ar * NN + ac + 8);                    \
    adjP[BUF_][3] = *(const float2*)(An_ + (size_t)(ar+8) * NN + ac + 8);                \
} while(0)

    #pragma unroll
    for (int q = 0; q < 16; q++) {
        const int row = q * 16 + rT;
        cp16(aY + row * EPB + cT * 16, yhi + ((size_t)b * NN + row) * HID + cT * 8);
    }
    #pragma unroll
    for (int q = 0; q < 8; q++) {
        const int row = q * 16 + rT;
        cp16(aW + row * EPB + cT * 16, wThi + (size_t)row * 128 + cT * 8);
    }
    CP_COMMIT();
    // overlap first adj loads with staging wait
    ADJ_LD(0, 0, 0);
    ADJ_LD(1, 0, 1);
    CP_WAIT(0); __syncthreads();

    float macc[16][4];
    #pragma unroll
    for (int j = 0; j < 16; j++)
        #pragma unroll
        for (int t = 0; t < 4; t++) macc[j][t] = 0.f;

    for (int k = 0; k < NK; k++) {
        float nacc[16][4];
        #pragma unroll
        for (int j = 0; j < 16; j++)
            #pragma unroll
            for (int t = 0; t < 4; t++) nacc[j][t] = 0.f;

        #pragma unroll
        for (int mc = 0; mc < 16; mc++) {
            uint32_t ah[4];
            #pragma unroll
            for (int q = 0; q < 4; q++)
                ah[q] = f22h2(adjP[mc&1][q].x, adjP[mc&1][q].y);
            // deep prefetch: 2 chunks ahead, wrapping into next bond type
            if (mc < 14) {
                ADJ_LD(mc&1, k, mc + 2);
            } else if (k < NK - 1) {
                ADJ_LD(mc&1, k + 1, mc - 14);
            }
            const uint32_t yb = aY + mc * 16 * EPB + lds_off;
            #pragma unroll
            for (int jj = 0; jj < 8; jj++) {
                uint32_t bh[4];
                ldsm_x4_t(bh, yb + jj * 32);
                mma_f16(nacc[2*jj],   ah, &bh[0]);
                mma_f16(nacc[2*jj+1], ah, &bh[2]);
            }
        }

        CP_WAIT(0); __syncthreads();   // W[k] resident (prefetched during prior GEMM1)

        #pragma unroll
        for (int hc = 0; hc < 8; hc++) {
            uint32_t ah[4];
            ah[0] = f22h2(nacc[2*hc][0],   nacc[2*hc][1]);
            ah[1] = f22h2(nacc[2*hc][2],   nacc[2*hc][3]);
            ah[2] = f22h2(nacc[2*hc+1][0], nacc[2*hc+1][1]);
            ah[3] = f22h2(nacc[2*hc+1][2], nacc[2*hc+1][3]);
            const uint32_t wb = aW + hc * 16 * EPB + lds_off;
            #pragma unroll
            for (int jj = 0; jj < 8; jj++) {
                uint32_t bh[4];
                ldsm_x4_t(bh, wb + jj * 32);
                mma_f16(macc[2*jj],   ah, &bh[0]);
                mma_f16(macc[2*jj+1], ah, &bh[2]);
            }
        }
        __syncthreads();
        if (k < NK - 1) {
            #pragma unroll
            for (int q = 0; q < 8; q++) {
                const int row = q * 16 + rT;
                cp16(aW + row * EPB + cT * 16,
                     wThi + ((size_t)(k + 1) << 14) + (size_t)row * 128 + cT * 8);
            }
            CP_COMMIT();
        }
    }

    // epilogue
    const int r0 = wrow + (lane >> 2);
    const int r1 = r0 + 8;
    const uint32_t* yh32 = (const uint32_t*)yhi;
    const uint32_t* yl32 = (const uint32_t*)ylo;
    float s0 = 0.f, q0 = 0.f, s1 = 0.f, q1 = 0.f;
    #pragma unroll
    for (int j = 0; j < 16; j++) {
        const int col = j * 8 + (lane & 3) * 2;
        const float2 e = *(const float2*)&ebsum[col];
        const size_t w0 = ((size_t)b * NN + r0) * HID + col;
        const size_t w1 = ((size_t)b * NN + r1) * HID + col;
        const float2 y0 = h2pairf(yh32[w0 >> 1], yl32[w0 >> 1]);
        const float2 y1 = h2pairf(yh32[w1 >> 1], yl32[w1 >> 1]);
        macc[j][0] += y0.x + e.x;  macc[j][1] += y0.y + e.y;
        macc[j][2] += y1.x + e.x;  macc[j][3] += y1.y + e.y;
        s0 += macc[j][0] + macc[j][1];
        q0 += macc[j][0]*macc[j][0] + macc[j][1]*macc[j][1];
        s1 += macc[j][2] + macc[j][3];
        q1 += macc[j][2]*macc[j][2] + macc[j][3]*macc[j][3];
    }
    #pragma unroll
    for (int d = 1; d <= 2; d <<= 1) {
        s0 += __shfl_xor_sync(0xffffffffu, s0, d);
        q0 += __shfl_xor_sync(0xffffffffu, q0, d);
        s1 += __shfl_xor_sync(0xffffffffu, s1, d);
        q1 += __shfl_xor_sync(0xffffffffu, q1, d);
    }
    const float mu0 = s0 * (1.f/HID), mu1 = s1 * (1.f/HID);
    const float ri0 = rsqrtf(q0 * (1.f/HID) - mu0*mu0 + LN_EPS);
    const float ri1 = rsqrtf(q1 * (1.f/HID) - mu1*mu1 + LN_EPS);

    #pragma unroll
    for (int j = 0; j < 16; j++) {
        const int col = j * 8 + (lane & 3) * 2;
        const float2 gg = *(const float2*)&lng[col];
        const float2 bb = *(const float2*)&lnb[col];
        const float o0 = fmaxf((macc[j][0]-mu0)*ri0*gg.x + bb.x, 0.f);
        const float o1 = fmaxf((macc[j][1]-mu0)*ri0*gg.y + bb.y, 0.f);
        const float o2 = fmaxf((macc[j][2]-mu1)*ri1*gg.x + bb.x, 0.f);
        const float o3 = fmaxf((macc[j][3]-mu1)*ri1*gg.y + bb.y, 0.f);
        const size_t w0 = ((size_t)b * NN + r0) * HID + col;
        const size_t w1 = ((size_t)b * NN + r1) * HID + col;
        if (last) {
            *(float2*)&xout[w0] = make_float2(o0, o1);
            *(float2*)&xout[w1] = make_float2(o2, o3);
        } else {
            uint16_t h0,l0,h1,l1;
            splith(o0,h0,l0); splith(o1,h1,l1);
            ((uint32_t*)xhi)[w0 >> 1] = packu(h0,h1);
            ((uint32_t*)xlo)[w0 >> 1] = packu(l0,l1);
            splith(o2,h0,l0); splith(o3,h1,l1);
            ((uint32_t*)xhi)[w1 >> 1] = packu(h0,h1);
            ((uint32_t*)xlo)[w1 >> 1] = packu(l0,l1);
        }
    }
#undef ADJ_LD
}

// ---------------------------------------------------------------------------------------
// Readout: 256 threads/block, float4 partials + smem atomics, then 16-wide out GEMV.
// ---------------------------------------------------------------------------------------
__global__ void readout_kernel(const float* __restrict__ x, const float* __restrict__ oW,
                               const float* __restrict__ ob, float* __restrict__ out)
{
    const int b = blockIdx.x;
    const int tid = threadIdx.x;
    const int half = tid >> 7;
    const int c4 = (tid & 127) >> 2;
    const int rr = tid & 3;
    float4 s = make_float4(0.f, 0.f, 0.f, 0.f);
    const float* xp = x + ((size_t)b * NN + half * 128) * HID + c4 * 4;
    #pragma unroll 4
    for (int n = rr; n < 128; n += 4) {
        const float4 v = *(const float4*)(xp + (size_t)n * HID);
        s.x += v.x; s.y += v.y; s.z += v.z; s.w += v.w;
    }
    __shared__ float repr[HID];
    if (tid < HID) repr[tid] = 0.f;
    __syncthreads();
    atomicAdd(&repr[c4 * 4 + 0], s.x);
    atomicAdd(&repr[c4 * 4 + 1], s.y);
    atomicAdd(&repr[c4 * 4 + 2], s.z);
    atomicAdd(&repr[c4 * 4 + 3], s.w);
    __syncthreads();
    if (tid < NOUT) {
        float acc = ob[tid];
        #pragma unroll 8
        for (int d = 0; d < HID; d++) acc += repr[d] * oW[tid * HID + d];
        out[b * NOUT + tid] = acc;
    }
}

// ---------------------------------------------------------------------------------------
extern "C" void kernel_launch(void* const* d_in, const int* in_sizes, int n_in,
                              void* d_out, int out_size)
{
    const float* feat = (const float*)d_in[0];
    const float* adj  = (const float*)d_in[1];
    const float* nW[3] = {(const float*)d_in[2], (const float*)d_in[4], (const float*)d_in[6]};
    const float* nb[3] = {(const float*)d_in[3], (const float*)d_in[5], (const float*)d_in[7]};
    const float* eW  = (const float*)d_in[8];
    const float* ebp = (const float*)d_in[9];
    const float* lng = (const float*)d_in[10];
    const float* lnb = (const float*)d_in[11];
    const float* oW  = (const float*)d_in[12];
    const float* ob  = (const float*)d_in[13];

    float *xb, *ebs;
    uint16_t *yhi, *ylo, *xhi, *xlo, *ewh, *nwh, *nwl;
    cudaGetSymbolAddress((void**)&yhi, g_yhi);
    cudaGetSymbolAddress((void**)&ylo, g_ylo);
    cudaGetSymbolAddress((void**)&xb,  g_x);
    cudaGetSymbolAddress((void**)&xhi, g_xhi);
    cudaGetSymbolAddress((void**)&xlo, g_xlo);
    cudaGetSymbolAddress((void**)&ewh, g_ewh);
    cudaGetSymbolAddress((void**)&nwh, g_nwh);
    cudaGetSymbolAddress((void**)&nwl, g_nwl);
    cudaGetSymbolAddress((void**)&ebs, g_ebsum);

    const int FUSED_SMEM = (256 + 128) * EPB;   // 104448 B
    const int LIN_SMEM   = 4 * 128 * EPB;       // 139264 B
    cudaFuncSetAttribute(fused_mp, cudaFuncAttributeMaxDynamicSharedMemorySize, FUSED_SMEM);
    cudaFuncSetAttribute(lin_mma,  cudaFuncAttributeMaxDynamicSharedMemorySize, LIN_SMEM);

    prep_wt_split<<<128*IND/256, 256>>>(nW[0], nwh, nwl, IND);
    prep_wt_split<<<128*HID/256, 256>>>(nW[1], nwh + 16384, nwl + 16384, HID);
    prep_wt_split<<<128*HID/256, 256>>>(nW[2], nwh + 32768, nwl + 32768, HID);
    prep_wt_hi<<<dim3(128*HID/256, NK), 256>>>(eW, ewh, HID);
    prep_feat<<<MM*IND/256, 256>>>(feat, xhi, xlo);
    prep_ebsum<<<1, HID>>>(ebp, ebs);

    int D = IND;
    for (int l = 0; l < NL; l++) {
        lin_mma<<<MM/128, 256, LIN_SMEM>>>(xhi, xlo, nwh + l*16384, nwl + l*16384,
                                           nb[l], yhi, ylo, D);
        fused_mp<<<dim3(2, BB), 256, FUSED_SMEM>>>(adj, yhi, ylo, ewh, ebs,
                                                   lng + l*HID, lnb + l*HID, xb, xhi, xlo,
                                                   (l == NL - 1) ? 1 : 0);
        D = HID;
    }
    readout_kernel<<<BB, 256>>>(xb, oW, ob, (float*)d_out);
}

// round 11
// speedup vs baseline: 1.8005x; 1.1239x over previous
#include <cuda_runtime.h>
#include <cuda_fp16.h>
#include <cstdint>

#define BB 256
#define NN 256
#define IND 64
#define HID 128
#define NOUT 16
#define NL 3
#define NK 4
#define MM (BB*NN)
#define LN_EPS 1e-5f
#define EP 136
#define EPB (EP*2)

__device__ uint16_t g_yhi[(size_t)MM * HID];        // plane buffer A
__device__ uint16_t g_ylo[(size_t)MM * HID];
__device__ uint16_t g_xhi[(size_t)MM * HID];        // plane buffer B
__device__ uint16_t g_xlo[(size_t)MM * HID];
__device__ float    g_x[(size_t)MM * HID];          // final fp32 for readout
__device__ uint16_t g_fhi[(size_t)MM * IND];        // feat planes
__device__ uint16_t g_flo[(size_t)MM * IND];
__device__ uint16_t g_ewh[(size_t)NK * HID * HID];
__device__ uint16_t g_nwh[(size_t)NL * HID * HID];
__device__ uint16_t g_nwl[(size_t)NL * HID * HID];
__device__ float    g_ebsum[HID];

__device__ __forceinline__ void splith(float a, uint16_t &h, uint16_t &l) {
    __half hh = __float2half_rn(a);
    __half ll = __float2half_rn(a - __half2float(hh));
    h = __half_as_ushort(hh); l = __half_as_ushort(ll);
}
__device__ __forceinline__ uint32_t packu(uint16_t a, uint16_t b) {
    return (uint32_t)a | ((uint32_t)b << 16);
}
__device__ __forceinline__ uint32_t f22h2(float x, float y) {
    __half2 h = __floats2half2_rn(x, y);
    return *(uint32_t*)&h;
}
__device__ __forceinline__ float2 h2pairf(uint32_t hbits, uint32_t lbits) {
    float2 a = __half22float2(*(__half2*)&hbits);
    float2 b = __half22float2(*(__half2*)&lbits);
    return make_float2(a.x + b.x, a.y + b.y);
}
__device__ __forceinline__ uint32_t cvta_s(const void* p) {
    return (uint32_t)__cvta_generic_to_shared(p);
}
__device__ __forceinline__ void ldsm_x4(uint32_t* r, uint32_t addr) {
    asm volatile("ldmatrix.sync.aligned.m8n8.x4.shared.b16 {%0,%1,%2,%3}, [%4];"
                 : "=r"(r[0]), "=r"(r[1]), "=r"(r[2]), "=r"(r[3]) : "r"(addr));
}
__device__ __forceinline__ void ldsm_x4_t(uint32_t* r, uint32_t addr) {
    asm volatile("ldmatrix.sync.aligned.m8n8.x4.trans.shared.b16 {%0,%1,%2,%3}, [%4];"
                 : "=r"(r[0]), "=r"(r[1]), "=r"(r[2]), "=r"(r[3]) : "r"(addr));
}
__device__ __forceinline__ void mma_f16(float* c, const uint32_t* a, const uint32_t* b) {
    asm volatile("mma.sync.aligned.m16n8k16.row.col.f32.f16.f16.f32 "
                 "{%0,%1,%2,%3}, {%4,%5,%6,%7}, {%8,%9}, {%0,%1,%2,%3};"
                 : "+f"(c[0]), "+f"(c[1]), "+f"(c[2]), "+f"(c[3])
                 : "r"(a[0]), "r"(a[1]), "r"(a[2]), "r"(a[3]), "r"(b[0]), "r"(b[1]));
}
__device__ __forceinline__ void cp16(uint32_t dst, const void* src) {
    asm volatile("cp.async.cg.shared.global [%0], [%1], 16;" :: "r"(dst), "l"(src));
}
#define CP_COMMIT() asm volatile("cp.async.commit_group;")
#define CP_WAIT(n)  asm volatile("cp.async.wait_group %0;" :: "n"(n))

// ---------------------------------------------------------------------------------------
__global__ void prep_wt_split(const float* __restrict__ src, uint16_t* __restrict__ hi,
                              uint16_t* __restrict__ lo, int D)
{
    const int idx = blockIdx.x * 256 + threadIdx.x;
    const int o = idx / D, d = idx % D;
    uint16_t h, l;
    splith(src[idx], h, l);
    const size_t dst = (size_t)d * 128 + o;
    hi[dst] = h; lo[dst] = l;
}

__global__ void prep_wt_hi(const float* __restrict__ src, uint16_t* __restrict__ hi, int D)
{
    const int idx = blockIdx.x * 256 + threadIdx.x;
    const int batch = blockIdx.y;
    const float* s = src + (size_t)batch * 128 * D;
    const int o = idx / D, d = idx % D;
    hi[(size_t)batch * D * 128 + (size_t)d * 128 + o] =
        __half_as_ushort(__float2half_rn(s[idx]));
}

__global__ void prep_feat(const float* __restrict__ f, uint16_t* __restrict__ hi,
                          uint16_t* __restrict__ lo)
{
    const int idx = blockIdx.x * 256 + threadIdx.x;
    uint16_t h, l;
    splith(f[idx], h, l);
    hi[idx] = h; lo[idx] = l;
}

__global__ void prep_ebsum(const float* __restrict__ eb, float* __restrict__ ebsum)
{
    const int h = threadIdx.x;
    ebsum[h] = eb[h] + eb[HID + h] + eb[2*HID + h] + eb[3*HID + h];
}

// ---------------------------------------------------------------------------------------
// Node linear (fp16 3-product) — layer 0 only now. (unchanged, validated)
// ---------------------------------------------------------------------------------------
__global__ __launch_bounds__(256, 1) void lin_mma(
    const uint16_t* __restrict__ xhi, const uint16_t* __restrict__ xlo,
    const uint16_t* __restrict__ wh, const uint16_t* __restrict__ wl,
    const float* __restrict__ bias,
    uint16_t* __restrict__ Yhi, uint16_t* __restrict__ Ylo, int D)
{
    extern __shared__ __align__(16) uint16_t lsm[];
    const uint32_t aX  = cvta_s(lsm);
    const uint32_t pX  = 128 * EPB;
    const uint32_t aW  = aX + 2 * 128 * EPB;
    const uint32_t pW  = 128 * EPB;

    const int m0 = blockIdx.x * 128;
    const int tid = threadIdx.x, warp = tid >> 5, lane = tid & 31;
    const int rT = tid >> 4, cT = tid & 15;
    const uint32_t lds_off = (lane & 15) * EPB + ((lane >> 4) << 4);

    const int dch = D >> 3;
    #pragma unroll
    for (int q = 0; q < 8; q++) {
        const int row = q * 16 + rT;
        if (cT < dch) {
            const size_t gi = (size_t)(m0 + row) * D + cT * 8;
            cp16(aX + row * EPB + cT * 16, xhi + gi);
            cp16(aX + pX + row * EPB + cT * 16, xlo + gi);
        }
    }
    for (int q = 0; q < (D >> 4); q++) {
        const int row = q * 16 + rT;
        const size_t gi = (size_t)row * 128 + cT * 8;
        cp16(aW + row * EPB + cT * 16, wh + gi);
        cp16(aW + pW + row * EPB + cT * 16, wl + gi);
    }
    CP_COMMIT(); CP_WAIT(0); __syncthreads();

    float macc[16][4];
    #pragma unroll
    for (int j = 0; j < 16; j++)
        #pragma unroll
        for (int t = 0; t < 4; t++) macc[j][t] = 0.f;

    for (int dc = 0; dc < (D >> 4); dc++) {
        uint32_t ah[4], al[4];
        const uint32_t axo = aX + (warp * 16 + (lane & 15)) * EPB + dc * 32 + ((lane >> 4) << 4);
        ldsm_x4(ah, axo);
        ldsm_x4(al, axo + pX);
        const uint32_t wb = aW + dc * 16 * EPB + lds_off;
        #pragma unroll
        for (int jj = 0; jj < 8; jj++) {
            uint32_t bh[4], bl[4];
            ldsm_x4_t(bh, wb + jj * 32);
            ldsm_x4_t(bl, wb + pW + jj * 32);
            #pragma unroll
            for (int tp = 0; tp < 2; tp++) {
                mma_f16(macc[2*jj+tp], ah, &bh[2*tp]);
                mma_f16(macc[2*jj+tp], ah, &bl[2*tp]);
                mma_f16(macc[2*jj+tp], al, &bh[2*tp]);
            }
        }
    }

    const int r0 = m0 + warp * 16 + (lane >> 2);
    #pragma unroll
    for (int j = 0; j < 16; j++) {
        const int col = j * 8 + (lane & 3) * 2;
        const float2 bb = *(const float2*)&bias[col];
        const float v0 = macc[j][0] + bb.x, v1 = macc[j][1] + bb.y;
        const float v2 = macc[j][2] + bb.x, v3 = macc[j][3] + bb.y;
        const size_t o0 = (size_t)r0 * HID + col;
        const size_t o1 = o0 + 8 * HID;
        uint16_t h0,l0,h1,l1;
        splith(v0,h0,l0); splith(v1,h1,l1);
        ((uint32_t*)Yhi)[o0 >> 1] = packu(h0,h1);
        ((uint32_t*)Ylo)[o0 >> 1] = packu(l0,l1);
        splith(v2,h0,l0); splith(v3,h1,l1);
        ((uint32_t*)Yhi)[o1 >> 1] = packu(h0,h1);
        ((uint32_t*)Ylo)[o1 >> 1] = packu(l0,l1);
    }
}

// ---------------------------------------------------------------------------------------
// Fused MP + LN + ReLU + (mode 0) next-layer node linear.
// mode 0: GEMM3 y' = x @ Wnode^T + b (3-product) -> write y' split planes (ping-pong).
// mode 1: write fp32 x for readout.
// ---------------------------------------------------------------------------------------
__global__ __launch_bounds__(256, 1) void fused_mp(
    const float* __restrict__ adj, const uint16_t* __restrict__ yhi,
    const uint16_t* __restrict__ ylo, const uint16_t* __restrict__ wThi,
    const float* __restrict__ ebsum, const float* __restrict__ lng,
    const float* __restrict__ lnb,
    const uint16_t* __restrict__ wnh, const uint16_t* __restrict__ wnl,
    const float* __restrict__ nbias,
    uint16_t* __restrict__ youth, uint16_t* __restrict__ youtl,
    float* __restrict__ xout, int mode)
{
    extern __shared__ __align__(16) uint16_t dsm[];
    const uint32_t aY = cvta_s(dsm);                 // 256 x EP (y hi; later Wnode hi+lo)
    const uint32_t aW = aY + 256 * EPB;              // 128 x EP (edge W hi)
    const uint32_t pN = 128 * EPB;                   // Wnode lo offset within aY region

    const int b = blockIdx.y;
    const int n0 = blockIdx.x * 128;
    const int tid = threadIdx.x, warp = tid >> 5, lane = tid & 31;
    const int wrow = n0 + warp * 16;
    const int rT = tid >> 4, cT = tid & 15;
    const int ar = lane >> 2, ac = (lane & 3) * 2;
    const uint32_t lds_off = (lane & 15) * EPB + ((lane >> 4) << 4);

    float2 adjP[2][4];
#define ADJ_LD(BUF_, KK_, MCC_) do {                                                     \
    const float* An_ = adj + (((size_t)(b * NK + (KK_)) * NN + wrow) * NN) + (MCC_) * 16;\
    adjP[BUF_][0] = *(const float2*)(An_ + (size_t)ar * NN + ac);                        \
    adjP[BUF_][1] = *(const float2*)(An_ + (size_t)(ar+8) * NN + ac);                    \
    adjP[BUF_][2] = *(const float2*)(An_ + (size_t)ar * NN + ac + 8);                    \
    adjP[BUF_][3] = *(const float2*)(An_ + (size_t)(ar+8) * NN + ac + 8);                \
} while(0)

    #pragma unroll
    for (int q = 0; q < 16; q++) {
        const int row = q * 16 + rT;
        cp16(aY + row * EPB + cT * 16, yhi + ((size_t)b * NN + row) * HID + cT * 8);
    }
    #pragma unroll
    for (int q = 0; q < 8; q++) {
        const int row = q * 16 + rT;
        cp16(aW + row * EPB + cT * 16, wThi + (size_t)row * 128 + cT * 8);
    }
    CP_COMMIT();
    ADJ_LD(0, 0, 0);
    ADJ_LD(1, 0, 1);
    CP_WAIT(0); __syncthreads();

    float macc[16][4];
    #pragma unroll
    for (int j = 0; j < 16; j++)
        #pragma unroll
        for (int t = 0; t < 4; t++) macc[j][t] = 0.f;

    for (int k = 0; k < NK; k++) {
        float nacc[16][4];
        #pragma unroll
        for (int j = 0; j < 16; j++)
            #pragma unroll
            for (int t = 0; t < 4; t++) nacc[j][t] = 0.f;

        #pragma unroll
        for (int mc = 0; mc < 16; mc++) {
            uint32_t ah[4];
            #pragma unroll
            for (int q = 0; q < 4; q++)
                ah[q] = f22h2(adjP[mc&1][q].x, adjP[mc&1][q].y);
            if (mc < 14) {
                ADJ_LD(mc&1, k, mc + 2);
            } else if (k < NK - 1) {
                ADJ_LD(mc&1, k + 1, mc - 14);
            }
            const uint32_t yb = aY + mc * 16 * EPB + lds_off;
            #pragma unroll
            for (int jj = 0; jj < 8; jj++) {
                uint32_t bh[4];
                ldsm_x4_t(bh, yb + jj * 32);
                mma_f16(nacc[2*jj],   ah, &bh[0]);
                mma_f16(nacc[2*jj+1], ah, &bh[2]);
            }
        }

        CP_WAIT(0); __syncthreads();   // W[k] resident; aY dead after last GEMM1

        // stage Wnode into aY region during GEMM2(k=3)+LN (mode 0 only)
        if (k == NK - 1 && mode == 0) {
            #pragma unroll
            for (int q = 0; q < 8; q++) {
                const int row = q * 16 + rT;
                cp16(aY + row * EPB + cT * 16,      wnh + (size_t)row * 128 + cT * 8);
                cp16(aY + pN + row * EPB + cT * 16, wnl + (size_t)row * 128 + cT * 8);
            }
            CP_COMMIT();
        }

        #pragma unroll
        for (int hc = 0; hc < 8; hc++) {
            uint32_t ah[4];
            ah[0] = f22h2(nacc[2*hc][0],   nacc[2*hc][1]);
            ah[1] = f22h2(nacc[2*hc][2],   nacc[2*hc][3]);
            ah[2] = f22h2(nacc[2*hc+1][0], nacc[2*hc+1][1]);
            ah[3] = f22h2(nacc[2*hc+1][2], nacc[2*hc+1][3]);
            const uint32_t wb = aW + hc * 16 * EPB + lds_off;
            #pragma unroll
            for (int jj = 0; jj < 8; jj++) {
                uint32_t bh[4];
                ldsm_x4_t(bh, wb + jj * 32);
                mma_f16(macc[2*jj],   ah, &bh[0]);
                mma_f16(macc[2*jj+1], ah, &bh[2]);
            }
        }
        __syncthreads();
        if (k < NK - 1) {
            #pragma unroll
            for (int q = 0; q < 8; q++) {
                const int row = q * 16 + rT;
                cp16(aW + row * EPB + cT * 16,
                     wThi + ((size_t)(k + 1) << 14) + (size_t)row * 128 + cT * 8);
            }
            CP_COMMIT();
        }
    }

    // -------- epilogue: residual + ebsum + LN + ReLU (x kept in macc) --------
    const int r0 = wrow + (lane >> 2);
    const int r1 = r0 + 8;
    const uint32_t* yh32 = (const uint32_t*)yhi;
    const uint32_t* yl32 = (const uint32_t*)ylo;
    float s0 = 0.f, q0 = 0.f, s1 = 0.f, q1 = 0.f;
    #pragma unroll
    for (int j = 0; j < 16; j++) {
        const int col = j * 8 + (lane & 3) * 2;
        const float2 e = *(const float2*)&ebsum[col];
        const size_t w0 = ((size_t)b * NN + r0) * HID + col;
        const size_t w1 = ((size_t)b * NN + r1) * HID + col;
        const float2 y0 = h2pairf(yh32[w0 >> 1], yl32[w0 >> 1]);
        const float2 y1 = h2pairf(yh32[w1 >> 1], yl32[w1 >> 1]);
        macc[j][0] += y0.x + e.x;  macc[j][1] += y0.y + e.y;
        macc[j][2] += y1.x + e.x;  macc[j][3] += y1.y + e.y;
        s0 += macc[j][0] + macc[j][1];
        q0 += macc[j][0]*macc[j][0] + macc[j][1]*macc[j][1];
        s1 += macc[j][2] + macc[j][3];
        q1 += macc[j][2]*macc[j][2] + macc[j][3]*macc[j][3];
    }
    #pragma unroll
    for (int d = 1; d <= 2; d <<= 1) {
        s0 += __shfl_xor_sync(0xffffffffu, s0, d);
        q0 += __shfl_xor_sync(0xffffffffu, q0, d);
        s1 += __shfl_xor_sync(0xffffffffu, s1, d);
        q1 += __shfl_xor_sync(0xffffffffu, q1, d);
    }
    const float mu0 = s0 * (1.f/HID), mu1 = s1 * (1.f/HID);
    const float ri0 = rsqrtf(q0 * (1.f/HID) - mu0*mu0 + LN_EPS);
    const float ri1 = rsqrtf(q1 * (1.f/HID) - mu1*mu1 + LN_EPS);

    #pragma unroll
    for (int j = 0; j < 16; j++) {
        const int col = j * 8 + (lane & 3) * 2;
        const float2 gg = *(const float2*)&lng[col];
        const float2 bb = *(const float2*)&lnb[col];
        macc[j][0] = fmaxf((macc[j][0]-mu0)*ri0*gg.x + bb.x, 0.f);
        macc[j][1] = fmaxf((macc[j][1]-mu0)*ri0*gg.y + bb.y, 0.f);
        macc[j][2] = fmaxf((macc[j][2]-mu1)*ri1*gg.x + bb.x, 0.f);
        macc[j][3] = fmaxf((macc[j][3]-mu1)*ri1*gg.y + bb.y, 0.f);
    }

    if (mode == 1) {
        #pragma unroll
        for (int j = 0; j < 16; j++) {
            const int col = j * 8 + (lane & 3) * 2;
            const size_t w0 = ((size_t)b * NN + r0) * HID + col;
            *(float2*)&xout[w0] = make_float2(macc[j][0], macc[j][1]);
            *(float2*)&xout[w0 + 8 * HID] = make_float2(macc[j][2], macc[j][3]);
        }
        return;
    }

    // -------- GEMM3: y' = x @ Wnode^T + b (3-product, x split in-register) --------
    CP_WAIT(0); __syncthreads();       // Wnode planes resident in aY region

    float yacc[16][4];
    #pragma unroll
    for (int j = 0; j < 16; j++)
        #pragma unroll
        for (int t = 0; t < 4; t++) yacc[j][t] = 0.f;

    #pragma unroll
    for (int kc = 0; kc < 8; kc++) {
        uint32_t ahh[4], ahl[4];
        uint16_t h0,l0,h1,l1;
        splith(macc[2*kc][0],h0,l0);   splith(macc[2*kc][1],h1,l1);
        ahh[0]=packu(h0,h1); ahl[0]=packu(l0,l1);
        splith(macc[2*kc][2],h0,l0);   splith(macc[2*kc][3],h1,l1);
        ahh[1]=packu(h0,h1); ahl[1]=packu(l0,l1);
        splith(macc[2*kc+1][0],h0,l0); splith(macc[2*kc+1][1],h1,l1);
        ahh[2]=packu(h0,h1); ahl[2]=packu(l0,l1);
        splith(macc[2*kc+1][2],h0,l0); splith(macc[2*kc+1][3],h1,l1);
        ahh[3]=packu(h0,h1); ahl[3]=packu(l0,l1);
        const uint32_t wb = aY + kc * 16 * EPB + lds_off;
        #pragma unroll
        for (int jj = 0; jj < 8; jj++) {
            uint32_t bh[4], bl[4];
            ldsm_x4_t(bh, wb + jj * 32);
            ldsm_x4_t(bl, wb + pN + jj * 32);
            #pragma unroll
            for (int tp = 0; tp < 2; tp++) {
                mma_f16(yacc[2*jj+tp], ahh, &bh[2*tp]);
                mma_f16(yacc[2*jj+tp], ahh, &bl[2*tp]);
                mma_f16(yacc[2*jj+tp], ahl, &bh[2*tp]);
            }
        }
    }

    #pragma unroll
    for (int j = 0; j < 16; j++) {
        const int col = j * 8 + (lane & 3) * 2;
        const float2 bb = *(const float2*)&nbias[col];
        const float v0 = yacc[j][0] + bb.x, v1 = yacc[j][1] + bb.y;
        const float v2 = yacc[j][2] + bb.x, v3 = yacc[j][3] + bb.y;
        const size_t w0 = ((size_t)b * NN + r0) * HID + col;
        const size_t w1 = ((size_t)b * NN + r1) * HID + col;
        uint16_t h0,l0,h1,l1;
        splith(v0,h0,l0); splith(v1,h1,l1);
        ((uint32_t*)youth)[w0 >> 1] = packu(h0,h1);
        ((uint32_t*)youtl)[w0 >> 1] = packu(l0,l1);
        splith(v2,h0,l0); splith(v3,h1,l1);
        ((uint32_t*)youth)[w1 >> 1] = packu(h0,h1);
        ((uint32_t*)youtl)[w1 >> 1] = packu(l0,l1);
    }
#undef ADJ_LD
}

// ---------------------------------------------------------------------------------------
__global__ void readout_kernel(const float* __restrict__ x, const float* __restrict__ oW,
                               const float* __restrict__ ob, float* __restrict__ out)
{
    const int b = blockIdx.x;
    const int tid = threadIdx.x;
    const int half = tid >> 7;
    const int c4 = (tid & 127) >> 2;
    const int rr = tid & 3;
    float4 s = make_float4(0.f, 0.f, 0.f, 0.f);
    const float* xp = x + ((size_t)b * NN + half * 128) * HID + c4 * 4;
    #pragma unroll 4
    for (int n = rr; n < 128; n += 4) {
        const float4 v = *(const float4*)(xp + (size_t)n * HID);
        s.x += v.x; s.y += v.y; s.z += v.z; s.w += v.w;
    }
    __shared__ float repr[HID];
    if (tid < HID) repr[tid] = 0.f;
    __syncthreads();
    atomicAdd(&repr[c4 * 4 + 0], s.x);
    atomicAdd(&repr[c4 * 4 + 1], s.y);
    atomicAdd(&repr[c4 * 4 + 2], s.z);
    atomicAdd(&repr[c4 * 4 + 3], s.w);
    __syncthreads();
    if (tid < NOUT) {
        float acc = ob[tid];
        #pragma unroll 8
        for (int d = 0; d < HID; d++) acc += repr[d] * oW[tid * HID + d];
        out[b * NOUT + tid] = acc;
    }
}

// ---------------------------------------------------------------------------------------
extern "C" void kernel_launch(void* const* d_in, const int* in_sizes, int n_in,
                              void* d_out, int out_size)
{
    const float* feat = (const float*)d_in[0];
    const float* adj  = (const float*)d_in[1];
    const float* nW[3] = {(const float*)d_in[2], (const float*)d_in[4], (const float*)d_in[6]};
    const float* nb[3] = {(const float*)d_in[3], (const float*)d_in[5], (const float*)d_in[7]};
    const float* eW  = (const float*)d_in[8];
    const float* ebp = (const float*)d_in[9];
    const float* lng = (const float*)d_in[10];
    const float* lnb = (const float*)d_in[11];
    const float* oW  = (const float*)d_in[12];
    const float* ob  = (const float*)d_in[13];

    float *xb, *ebs;
    uint16_t *yAh, *yAl, *yBh, *yBl, *fhi, *flo, *ewh, *nwh, *nwl;
    cudaGetSymbolAddress((void**)&yAh, g_yhi);
    cudaGetSymbolAddress((void**)&yAl, g_ylo);
    cudaGetSymbolAddress((void**)&yBh, g_xhi);
    cudaGetSymbolAddress((void**)&yBl, g_xlo);
    cudaGetSymbolAddress((void**)&xb,  g_x);
    cudaGetSymbolAddress((void**)&fhi, g_fhi);
    cudaGetSymbolAddress((void**)&flo, g_flo);
    cudaGetSymbolAddress((void**)&ewh, g_ewh);
    cudaGetSymbolAddress((void**)&nwh, g_nwh);
    cudaGetSymbolAddress((void**)&nwl, g_nwl);
    cudaGetSymbolAddress((void**)&ebs, g_ebsum);

    const int FUSED_SMEM = (256 + 128) * EPB;   // 104448 B
    const int LIN_SMEM   = 4 * 128 * EPB;       // 139264 B
    cudaFuncSetAttribute(fused_mp, cudaFuncAttributeMaxDynamicSharedMemorySize, FUSED_SMEM);
    cudaFuncSetAttribute(lin_mma,  cudaFuncAttributeMaxDynamicSharedMemorySize, LIN_SMEM);

    prep_wt_split<<<128*IND/256, 256>>>(nW[0], nwh, nwl, IND);
    prep_wt_split<<<128*HID/256, 256>>>(nW[1], nwh + 16384, nwl + 16384, HID);
    prep_wt_split<<<128*HID/256, 256>>>(nW[2], nwh + 32768, nwl + 32768, HID);
    prep_wt_hi<<<dim3(128*HID/256, NK), 256>>>(eW, ewh, HID);
    prep_feat<<<MM*IND/256, 256>>>(feat, fhi, flo);
    prep_ebsum<<<1, HID>>>(ebp, ebs);

    // layer 0 node linear: feat -> yA
    lin_mma<<<MM/128, 256, LIN_SMEM>>>(fhi, flo, nwh, nwl, nb[0], yAh, yAl, IND);
    // layer 0 MP (+node linear for layer 1): yA -> yB
    fused_mp<<<dim3(2, BB), 256, FUSED_SMEM>>>(adj, yAh, yAl, ewh, ebs,
                                               lng, lnb,
                                               nwh + 16384, nwl + 16384, nb[1],
                                               yBh, yBl, xb, 0);
    // layer 1 MP (+node linear for layer 2): yB -> yA
    fused_mp<<<dim3(2, BB), 256, FUSED_SMEM>>>(adj, yBh, yBl, ewh, ebs,
                                               lng + HID, lnb + HID,
                                               nwh + 32768, nwl + 32768, nb[2],
                                               yAh, yAl, xb, 0);
    // layer 2 MP -> fp32 x
    fused_mp<<<dim3(2, BB), 256, FUSED_SMEM>>>(adj, yAh, yAl, ewh, ebs,
                                               lng + 2*HID, lnb + 2*HID,
                                               nwh, nwl, nb[0],
                                               yBh, yBl, xb, 1);
    readout_kernel<<<BB, 256>>>(xb, oW, ob, (float*)d_out);
}

// round 12
// speedup vs baseline: 1.8141x; 1.0075x over previous
#include <cuda_runtime.h>
#include <cuda_fp16.h>
#include <cstdint>

#define BB 256
#define NN 256
#define IND 64
#define HID 128
#define NOUT 16
#define NL 3
#define NK 4
#define MM (BB*NN)
#define LN_EPS 1e-5f
#define EP 136
#define EPB (EP*2)

__device__ uint16_t g_yhi[(size_t)MM * HID];        // plane buffer A
__device__ uint16_t g_ylo[(size_t)MM * HID];
__device__ uint16_t g_xhi[(size_t)MM * HID];        // plane buffer B
__device__ uint16_t g_xlo[(size_t)MM * HID];
__device__ float    g_x[(size_t)MM * HID];          // final fp32 for readout
__device__ uint16_t g_fhi[(size_t)MM * IND];        // feat planes
__device__ uint16_t g_flo[(size_t)MM * IND];
__device__ uint16_t g_ewh[(size_t)NK * HID * HID];
__device__ uint16_t g_nwh[(size_t)NL * HID * HID];
__device__ uint16_t g_nwl[(size_t)NL * HID * HID];
__device__ float    g_ebsum[HID];

__device__ __forceinline__ void splith(float a, uint16_t &h, uint16_t &l) {
    __half hh = __float2half_rn(a);
    __half ll = __float2half_rn(a - __half2float(hh));
    h = __half_as_ushort(hh); l = __half_as_ushort(ll);
}
__device__ __forceinline__ uint32_t packu(uint16_t a, uint16_t b) {
    return (uint32_t)a | ((uint32_t)b << 16);
}
__device__ __forceinline__ uint32_t f22h2(float x, float y) {
    __half2 h = __floats2half2_rn(x, y);
    return *(uint32_t*)&h;
}
__device__ __forceinline__ float2 h2pairf(uint32_t hbits, uint32_t lbits) {
    float2 a = __half22float2(*(__half2*)&hbits);
    float2 b = __half22float2(*(__half2*)&lbits);
    return make_float2(a.x + b.x, a.y + b.y);
}
__device__ __forceinline__ uint32_t cvta_s(const void* p) {
    return (uint32_t)__cvta_generic_to_shared(p);
}
__device__ __forceinline__ void ldsm_x4(uint32_t* r, uint32_t addr) {
    asm volatile("ldmatrix.sync.aligned.m8n8.x4.shared.b16 {%0,%1,%2,%3}, [%4];"
                 : "=r"(r[0]), "=r"(r[1]), "=r"(r[2]), "=r"(r[3]) : "r"(addr));
}
__device__ __forceinline__ void ldsm_x4_t(uint32_t* r, uint32_t addr) {
    asm volatile("ldmatrix.sync.aligned.m8n8.x4.trans.shared.b16 {%0,%1,%2,%3}, [%4];"
                 : "=r"(r[0]), "=r"(r[1]), "=r"(r[2]), "=r"(r[3]) : "r"(addr));
}
__device__ __forceinline__ void mma_f16(float* c, const uint32_t* a, const uint32_t* b) {
    asm volatile("mma.sync.aligned.m16n8k16.row.col.f32.f16.f16.f32 "
                 "{%0,%1,%2,%3}, {%4,%5,%6,%7}, {%8,%9}, {%0,%1,%2,%3};"
                 : "+f"(c[0]), "+f"(c[1]), "+f"(c[2]), "+f"(c[3])
                 : "r"(a[0]), "r"(a[1]), "r"(a[2]), "r"(a[3]), "r"(b[0]), "r"(b[1]));
}
__device__ __forceinline__ void cp16(uint32_t dst, const void* src) {
    asm volatile("cp.async.cg.shared.global [%0], [%1], 16;" :: "r"(dst), "l"(src));
}
#define CP_COMMIT() asm volatile("cp.async.commit_group;")
#define CP_WAIT(n)  asm volatile("cp.async.wait_group %0;" :: "n"(n))

// ---------------------------------------------------------------------------------------
// Merged weight prep (single launch): node W0/W1/W2 split planes + edge W hi planes.
// grid = 416 blocks x 256 threads, segmented by blockIdx.x.
// ---------------------------------------------------------------------------------------
__global__ void prep_weights(const float* __restrict__ nW0, const float* __restrict__ nW1,
                             const float* __restrict__ nW2, const float* __restrict__ eW,
                             uint16_t* __restrict__ nwh, uint16_t* __restrict__ nwl,
                             uint16_t* __restrict__ ewh)
{
    const int bid = blockIdx.x, tid = threadIdx.x;
    if (bid < 32) {                       // nW0: 128x64
        const int idx = bid * 256 + tid;
        const int o = idx >> 6, d = idx & 63;
        uint16_t h, l; splith(nW0[idx], h, l);
        nwh[d * 128 + o] = h; nwl[d * 128 + o] = l;
    } else if (bid < 96) {                // nW1: 128x128
        const int idx = (bid - 32) * 256 + tid;
        const int o = idx >> 7, d = idx & 127;
        uint16_t h, l; splith(nW1[idx], h, l);
        nwh[16384 + d * 128 + o] = h; nwl[16384 + d * 128 + o] = l;
    } else if (bid < 160) {               // nW2: 128x128
        const int idx = (bid - 96) * 256 + tid;
        const int o = idx >> 7, d = idx & 127;
        uint16_t h, l; splith(nW2[idx], h, l);
        nwh[32768 + d * 128 + o] = h; nwl[32768 + d * 128 + o] = l;
    } else {                              // eW: 4 x 128x128, hi only
        const int idx = (bid - 160) * 256 + tid;
        const int k = idx >> 14, rem = idx & 16383;
        const int o = rem >> 7, d = rem & 127;
        ewh[(k << 14) + d * 128 + o] = __half_as_ushort(__float2half_rn(eW[idx]));
    }
}

__global__ void prep_feat(const float* __restrict__ f, uint16_t* __restrict__ hi,
                          uint16_t* __restrict__ lo)
{
    const int idx = blockIdx.x * 256 + threadIdx.x;
    uint16_t h, l;
    splith(f[idx], h, l);
    hi[idx] = h; lo[idx] = l;
}

__global__ void prep_ebsum(const float* __restrict__ eb, float* __restrict__ ebsum)
{
    const int h = threadIdx.x;
    ebsum[h] = eb[h] + eb[HID + h] + eb[2*HID + h] + eb[3*HID + h];
}

// ---------------------------------------------------------------------------------------
// Node linear (fp16 3-product) — layer 0 only. (unchanged, validated)
// ---------------------------------------------------------------------------------------
__global__ __launch_bounds__(256, 1) void lin_mma(
    const uint16_t* __restrict__ xhi, const uint16_t* __restrict__ xlo,
    const uint16_t* __restrict__ wh, const uint16_t* __restrict__ wl,
    const float* __restrict__ bias,
    uint16_t* __restrict__ Yhi, uint16_t* __restrict__ Ylo, int D)
{
    extern __shared__ __align__(16) uint16_t lsm[];
    const uint32_t aX  = cvta_s(lsm);
    const uint32_t pX  = 128 * EPB;
    const uint32_t aW  = aX + 2 * 128 * EPB;
    const uint32_t pW  = 128 * EPB;

    const int m0 = blockIdx.x * 128;
    const int tid = threadIdx.x, warp = tid >> 5, lane = tid & 31;
    const int rT = tid >> 4, cT = tid & 15;
    const uint32_t lds_off = (lane & 15) * EPB + ((lane >> 4) << 4);

    const int dch = D >> 3;
    #pragma unroll
    for (int q = 0; q < 8; q++) {
        const int row = q * 16 + rT;
        if (cT < dch) {
            const size_t gi = (size_t)(m0 + row) * D + cT * 8;
            cp16(aX + row * EPB + cT * 16, xhi + gi);
            cp16(aX + pX + row * EPB + cT * 16, xlo + gi);
        }
    }
    for (int q = 0; q < (D >> 4); q++) {
        const int row = q * 16 + rT;
        const size_t gi = (size_t)row * 128 + cT * 8;
        cp16(aW + row * EPB + cT * 16, wh + gi);
        cp16(aW + pW + row * EPB + cT * 16, wl + gi);
    }
    CP_COMMIT(); CP_WAIT(0); __syncthreads();

    float macc[16][4];
    #pragma unroll
    for (int j = 0; j < 16; j++)
        #pragma unroll
        for (int t = 0; t < 4; t++) macc[j][t] = 0.f;

    for (int dc = 0; dc < (D >> 4); dc++) {
        uint32_t ah[4], al[4];
        const uint32_t axo = aX + (warp * 16 + (lane & 15)) * EPB + dc * 32 + ((lane >> 4) << 4);
        ldsm_x4(ah, axo);
        ldsm_x4(al, axo + pX);
        const uint32_t wb = aW + dc * 16 * EPB + lds_off;
        #pragma unroll
        for (int jj = 0; jj < 8; jj++) {
            uint32_t bh[4], bl[4];
            ldsm_x4_t(bh, wb + jj * 32);
            ldsm_x4_t(bl, wb + pW + jj * 32);
            #pragma unroll
            for (int tp = 0; tp < 2; tp++) {
                mma_f16(macc[2*jj+tp], ah, &bh[2*tp]);
                mma_f16(macc[2*jj+tp], ah, &bl[2*tp]);
                mma_f16(macc[2*jj+tp], al, &bh[2*tp]);
            }
        }
    }

    const int r0 = m0 + warp * 16 + (lane >> 2);
    #pragma unroll
    for (int j = 0; j < 16; j++) {
        const int col = j * 8 + (lane & 3) * 2;
        const float2 bb = *(const float2*)&bias[col];
        const float v0 = macc[j][0] + bb.x, v1 = macc[j][1] + bb.y;
        const float v2 = macc[j][2] + bb.x, v3 = macc[j][3] + bb.y;
        const size_t o0 = (size_t)r0 * HID + col;
        const size_t o1 = o0 + 8 * HID;
        uint16_t h0,l0,h1,l1;
        splith(v0,h0,l0); splith(v1,h1,l1);
        ((uint32_t*)Yhi)[o0 >> 1] = packu(h0,h1);
        ((uint32_t*)Ylo)[o0 >> 1] = packu(l0,l1);
        splith(v2,h0,l0); splith(v3,h1,l1);
        ((uint32_t*)Yhi)[o1 >> 1] = packu(h0,h1);
        ((uint32_t*)Ylo)[o1 >> 1] = packu(l0,l1);
    }
}

// ---------------------------------------------------------------------------------------
// Fused MP + LN + ReLU + (mode 0) next-layer node linear.
// All 4 edge-W hi planes resident in smem (staged once) -> zero syncs in k-loop (k<3).
// ---------------------------------------------------------------------------------------
__global__ __launch_bounds__(256, 1) void fused_mp(
    const float* __restrict__ adj, const uint16_t* __restrict__ yhi,
    const uint16_t* __restrict__ ylo, const uint16_t* __restrict__ wThi,
    const float* __restrict__ ebsum, const float* __restrict__ lng,
    const float* __restrict__ lnb,
    const uint16_t* __restrict__ wnh, const uint16_t* __restrict__ wnl,
    const float* __restrict__ nbias,
    uint16_t* __restrict__ youth, uint16_t* __restrict__ youtl,
    float* __restrict__ xout, int mode)
{
    extern __shared__ __align__(16) uint16_t dsm[];
    const uint32_t aY = cvta_s(dsm);                 // 256 x EP (y hi; later Wnode hi+lo)
    const uint32_t aW = aY + 256 * EPB;              // 512 x EP (all 4 edge-W hi)
    const uint32_t pN = 128 * EPB;                   // Wnode lo offset within aY region

    const int b = blockIdx.y;
    const int n0 = blockIdx.x * 128;
    const int tid = threadIdx.x, warp = tid >> 5, lane = tid & 31;
    const int wrow = n0 + warp * 16;
    const int rT = tid >> 4, cT = tid & 15;
    const int ar = lane >> 2, ac = (lane & 3) * 2;
    const uint32_t lds_off = (lane & 15) * EPB + ((lane >> 4) << 4);

    float2 adjP[2][4];
#define ADJ_LD(BUF_, KK_, MCC_) do {                                                     \
    const float* An_ = adj + (((size_t)(b * NK + (KK_)) * NN + wrow) * NN) + (MCC_) * 16;\
    adjP[BUF_][0] = *(const float2*)(An_ + (size_t)ar * NN + ac);                        \
    adjP[BUF_][1] = *(const float2*)(An_ + (size_t)(ar+8) * NN + ac);                    \
    adjP[BUF_][2] = *(const float2*)(An_ + (size_t)ar * NN + ac + 8);                    \
    adjP[BUF_][3] = *(const float2*)(An_ + (size_t)(ar+8) * NN + ac + 8);                \
} while(0)

    // stage y tile (256 rows) + ALL 4 edge-W hi planes (512 rows)
    #pragma unroll
    for (int q = 0; q < 16; q++) {
        const int row = q * 16 + rT;
        cp16(aY + row * EPB + cT * 16, yhi + ((size_t)b * NN + row) * HID + cT * 8);
    }
    #pragma unroll
    for (int q = 0; q < 32; q++) {
        const int row = q * 16 + rT;                 // 0..511 over [k][d] rows
        cp16(aW + row * EPB + cT * 16, wThi + (size_t)row * 128 + cT * 8);
    }
    CP_COMMIT();
    ADJ_LD(0, 0, 0);
    ADJ_LD(1, 0, 1);
    CP_WAIT(0); __syncthreads();

    float macc[16][4];
    #pragma unroll
    for (int j = 0; j < 16; j++)
        #pragma unroll
        for (int t = 0; t < 4; t++) macc[j][t] = 0.f;

    for (int k = 0; k < NK; k++) {
        float nacc[16][4];
        #pragma unroll
        for (int j = 0; j < 16; j++)
            #pragma unroll
            for (int t = 0; t < 4; t++) nacc[j][t] = 0.f;

        #pragma unroll
        for (int mc = 0; mc < 16; mc++) {
            uint32_t ah[4];
            #pragma unroll
            for (int q = 0; q < 4; q++)
                ah[q] = f22h2(adjP[mc&1][q].x, adjP[mc&1][q].y);
            if (mc < 14) {
                ADJ_LD(mc&1, k, mc + 2);
            } else if (k < NK - 1) {
                ADJ_LD(mc&1, k + 1, mc - 14);
            }
            const uint32_t yb = aY + mc * 16 * EPB + lds_off;
            #pragma unroll
            for (int jj = 0; jj < 8; jj++) {
                uint32_t bh[4];
                ldsm_x4_t(bh, yb + jj * 32);
                mma_f16(nacc[2*jj],   ah, &bh[0]);
                mma_f16(nacc[2*jj+1], ah, &bh[2]);
            }
        }

        // at the last k, aY becomes dead -> stage Wnode planes there (mode 0)
        if (k == NK - 1 && mode == 0) {
            __syncthreads();                         // all warps done reading aY
            #pragma unroll
            for (int q = 0; q < 8; q++) {
                const int row = q * 16 + rT;
                cp16(aY + row * EPB + cT * 16,      wnh + (size_t)row * 128 + cT * 8);
                cp16(aY + pN + row * EPB + cT * 16, wnl + (size_t)row * 128 + cT * 8);
            }
            CP_COMMIT();
        }

        const uint32_t wslot = aW + (uint32_t)k * 128 * EPB;
        #pragma unroll
        for (int hc = 0; hc < 8; hc++) {
            uint32_t ah[4];
            ah[0] = f22h2(nacc[2*hc][0],   nacc[2*hc][1]);
            ah[1] = f22h2(nacc[2*hc][2],   nacc[2*hc][3]);
            ah[2] = f22h2(nacc[2*hc+1][0], nacc[2*hc+1][1]);
            ah[3] = f22h2(nacc[2*hc+1][2], nacc[2*hc+1][3]);
            const uint32_t wb = wslot + hc * 16 * EPB + lds_off;
            #pragma unroll
            for (int jj = 0; jj < 8; jj++) {
                uint32_t bh[4];
                ldsm_x4_t(bh, wb + jj * 32);
                mma_f16(macc[2*jj],   ah, &bh[0]);
                mma_f16(macc[2*jj+1], ah, &bh[2]);
            }
        }
    }

    // -------- epilogue: residual + ebsum + LN + ReLU (x kept in macc) --------
    const int r0 = wrow + (lane >> 2);
    const int r1 = r0 + 8;
    const uint32_t* yh32 = (const uint32_t*)yhi;
    const uint32_t* yl32 = (const uint32_t*)ylo;
    float s0 = 0.f, q0 = 0.f, s1 = 0.f, q1 = 0.f;
    #pragma unroll
    for (int j = 0; j < 16; j++) {
        const int col = j * 8 + (lane & 3) * 2;
        const float2 e = *(const float2*)&ebsum[col];
        const size_t w0 = ((size_t)b * NN + r0) * HID + col;
        const size_t w1 = ((size_t)b * NN + r1) * HID + col;
        const float2 y0 = h2pairf(yh32[w0 >> 1], yl32[w0 >> 1]);
        const float2 y1 = h2pairf(yh32[w1 >> 1], yl32[w1 >> 1]);
        macc[j][0] += y0.x + e.x;  macc[j][1] += y0.y + e.y;
        macc[j][2] += y1.x + e.x;  macc[j][3] += y1.y + e.y;
        s0 += macc[j][0] + macc[j][1];
        q0 += macc[j][0]*macc[j][0] + macc[j][1]*macc[j][1];
        s1 += macc[j][2] + macc[j][3];
        q1 += macc[j][2]*macc[j][2] + macc[j][3]*macc[j][3];
    }
    #pragma unroll
    for (int d = 1; d <= 2; d <<= 1) {
        s0 += __shfl_xor_sync(0xffffffffu, s0, d);
        q0 += __shfl_xor_sync(0xffffffffu, q0, d);
        s1 += __shfl_xor_sync(0xffffffffu, s1, d);
        q1 += __shfl_xor_sync(0xffffffffu, q1, d);
    }
    const float mu0 = s0 * (1.f/HID), mu1 = s1 * (1.f/HID);
    const float ri0 = rsqrtf(q0 * (1.f/HID) - mu0*mu0 + LN_EPS);
    const float ri1 = rsqrtf(q1 * (1.f/HID) - mu1*mu1 + LN_EPS);

    #pragma unroll
    for (int j = 0; j < 16; j++) {
        const int col = j * 8 + (lane & 3) * 2;
        const float2 gg = *(const float2*)&lng[col];
        const float2 bb = *(const float2*)&lnb[col];
        macc[j][0] = fmaxf((macc[j][0]-mu0)*ri0*gg.x + bb.x, 0.f);
        macc[j][1] = fmaxf((macc[j][1]-mu0)*ri0*gg.y + bb.y, 0.f);
        macc[j][2] = fmaxf((macc[j][2]-mu1)*ri1*gg.x + bb.x, 0.f);
        macc[j][3] = fmaxf((macc[j][3]-mu1)*ri1*gg.y + bb.y, 0.f);
    }

    if (mode == 1) {
        #pragma unroll
        for (int j = 0; j < 16; j++) {
            const int col = j * 8 + (lane & 3) * 2;
            const size_t w0 = ((size_t)b * NN + r0) * HID + col;
            *(float2*)&xout[w0] = make_float2(macc[j][0], macc[j][1]);
            *(float2*)&xout[w0 + 8 * HID] = make_float2(macc[j][2], macc[j][3]);
        }
        return;
    }

    // -------- GEMM3: y' = x @ Wnode^T + b (3-product, x split in-register) --------
    CP_WAIT(0); __syncthreads();       // Wnode planes resident in aY region

    float yacc[16][4];
    #pragma unroll
    for (int j = 0; j < 16; j++)
        #pragma unroll
        for (int t = 0; t < 4; t++) yacc[j][t] = 0.f;

    #pragma unroll
    for (int kc = 0; kc < 8; kc++) {
        uint32_t ahh[4], ahl[4];
        uint16_t h0,l0,h1,l1;
        splith(macc[2*kc][0],h0,l0);   splith(macc[2*kc][1],h1,l1);
        ahh[0]=packu(h0,h1); ahl[0]=packu(l0,l1);
        splith(macc[2*kc][2],h0,l0);   splith(macc[2*kc][3],h1,l1);
        ahh[1]=packu(h0,h1); ahl[1]=packu(l0,l1);
        splith(macc[2*kc+1][0],h0,l0); splith(macc[2*kc+1][1],h1,l1);
        ahh[2]=packu(h0,h1); ahl[2]=packu(l0,l1);
        splith(macc[2*kc+1][2],h0,l0); splith(macc[2*kc+1][3],h1,l1);
        ahh[3]=packu(h0,h1); ahl[3]=packu(l0,l1);
        const uint32_t wb = aY + kc * 16 * EPB + lds_off;
        #pragma unroll
        for (int jj = 0; jj < 8; jj++) {
            uint32_t bh[4], bl[4];
            ldsm_x4_t(bh, wb + jj * 32);
            ldsm_x4_t(bl, wb + pN + jj * 32);
            #pragma unroll
            for (int tp = 0; tp < 2; tp++) {
                mma_f16(yacc[2*jj+tp], ahh, &bh[2*tp]);
                mma_f16(yacc[2*jj+tp], ahh, &bl[2*tp]);
                mma_f16(yacc[2*jj+tp], ahl, &bh[2*tp]);
            }
        }
    }

    #pragma unroll
    for (int j = 0; j < 16; j++) {
        const int col = j * 8 + (lane & 3) * 2;
        const float2 bb = *(const float2*)&nbias[col];
        const float v0 = yacc[j][0] + bb.x, v1 = yacc[j][1] + bb.y;
        const float v2 = yacc[j][2] + bb.x, v3 = yacc[j][3] + bb.y;
        const size_t w0 = ((size_t)b * NN + r0) * HID + col;
        const size_t w1 = ((size_t)b * NN + r1) * HID + col;
        uint16_t h0,l0,h1,l1;
        splith(v0,h0,l0); splith(v1,h1,l1);
        ((uint32_t*)youth)[w0 >> 1] = packu(h0,h1);
        ((uint32_t*)youtl)[w0 >> 1] = packu(l0,l1);
        splith(v2,h0,l0); splith(v3,h1,l1);
        ((uint32_t*)youth)[w1 >> 1] = packu(h0,h1);
        ((uint32_t*)youtl)[w1 >> 1] = packu(l0,l1);
    }
#undef ADJ_LD
}

// ---------------------------------------------------------------------------------------
__global__ void readout_kernel(const float* __restrict__ x, const float* __restrict__ oW,
                               const float* __restrict__ ob, float* __restrict__ out)
{
    const int b = blockIdx.x;
    const int tid = threadIdx.x;
    const int half = tid >> 7;
    const int c4 = (tid & 127) >> 2;
    const int rr = tid & 3;
    float4 s = make_float4(0.f, 0.f, 0.f, 0.f);
    const float* xp = x + ((size_t)b * NN + half * 128) * HID + c4 * 4;
    #pragma unroll 4
    for (int n = rr; n < 128; n += 4) {
        const float4 v = *(const float4*)(xp + (size_t)n * HID);
        s.x += v.x; s.y += v.y; s.z += v.z; s.w += v.w;
    }
    __shared__ float repr[HID];
    if (tid < HID) repr[tid] = 0.f;
    __syncthreads();
    atomicAdd(&repr[c4 * 4 + 0], s.x);
    atomicAdd(&repr[c4 * 4 + 1], s.y);
    atomicAdd(&repr[c4 * 4 + 2], s.z);
    atomicAdd(&repr[c4 * 4 + 3], s.w);
    __syncthreads();
    if (tid < NOUT) {
        float acc = ob[tid];
        #pragma unroll 8
        for (int d = 0; d < HID; d++) acc += repr[d] * oW[tid * HID + d];
        out[b * NOUT + tid] = acc;
    }
}

// ---------------------------------------------------------------------------------------
extern "C" void kernel_launch(void* const* d_in, const int* in_sizes, int n_in,
                              void* d_out, int out_size)
{
    const float* feat = (const float*)d_in[0];
    const float* adj  = (const float*)d_in[1];
    const float* nW[3] = {(const float*)d_in[2], (const float*)d_in[4], (const float*)d_in[6]};
    const float* nb[3] = {(const float*)d_in[3], (const float*)d_in[5], (const float*)d_in[7]};
    const float* eW  = (const float*)d_in[8];
    const float* ebp = (const float*)d_in[9];
    const float* lng = (const float*)d_in[10];
    const float* lnb = (const float*)d_in[11];
    const float* oW  = (const float*)d_in[12];
    const float* ob  = (const float*)d_in[13];

    float *xb, *ebs;
    uint16_t *yAh, *yAl, *yBh, *yBl, *fhi, *flo, *ewh, *nwh, *nwl;
    cudaGetSymbolAddress((void**)&yAh, g_yhi);
    cudaGetSymbolAddress((void**)&yAl, g_ylo);
    cudaGetSymbolAddress((void**)&yBh, g_xhi);
    cudaGetSymbolAddress((void**)&yBl, g_xlo);
    cudaGetSymbolAddress((void**)&xb,  g_x);
    cudaGetSymbolAddress((void**)&fhi, g_fhi);
    cudaGetSymbolAddress((void**)&flo, g_flo);
    cudaGetSymbolAddress((void**)&ewh, g_ewh);
    cudaGetSymbolAddress((void**)&nwh, g_nwh);
    cudaGetSymbolAddress((void**)&nwl, g_nwl);
    cudaGetSymbolAddress((void**)&ebs, g_ebsum);

    const int FUSED_SMEM = (256 + 512) * EPB;   // 208896 B (y + all 4 edge W)
    const int LIN_SMEM   = 4 * 128 * EPB;       // 139264 B
    cudaFuncSetAttribute(fused_mp, cudaFuncAttributeMaxDynamicSharedMemorySize, FUSED_SMEM);
    cudaFuncSetAttribute(lin_mma,  cudaFuncAttributeMaxDynamicSharedMemorySize, LIN_SMEM);

    // 3 prep launches -> fused_mp #2 is the 6th kernel (ncu -s 5 -c 1 captures it)
    prep_weights<<<416, 256>>>(nW[0], nW[1], nW[2], eW, nwh, nwl, ewh);
    prep_feat<<<MM*IND/256, 256>>>(feat, fhi, flo);
    prep_ebsum<<<1, HID>>>(ebp, ebs);

    // layer 0 node linear: feat -> yA
    lin_mma<<<MM/128, 256, LIN_SMEM>>>(fhi, flo, nwh, nwl, nb[0], yAh, yAl, IND);
    // layer 0 MP (+node linear for layer 1): yA -> yB
    fused_mp<<<dim3(2, BB), 256, FUSED_SMEM>>>(adj, yAh, yAl, ewh, ebs,
                                               lng, lnb,
                                               nwh + 16384, nwl + 16384, nb[1],
                                               yBh, yBl, xb, 0);
    // layer 1 MP (+node linear for layer 2): yB -> yA   <-- profiled launch
    fused_mp<<<dim3(2, BB), 256, FUSED_SMEM>>>(adj, yBh, yBl, ewh, ebs,
                                               lng + HID, lnb + HID,
                                               nwh + 32768, nwl + 32768, nb[2],
                                               yAh, yAl, xb, 0);
    // layer 2 MP -> fp32 x
    fused_mp<<<dim3(2, BB), 256, FUSED_SMEM>>>(adj, yAh, yAl, ewh, ebs,
                                               lng + 2*HID, lnb + 2*HID,
                                               nwh, nwl, nb[0],
                                               yBh, yBl, xb, 1);
    readout_kernel<<<BB, 256>>>(xb, oW, ob, (float*)d_out);
}